// round 2
// baseline (speedup 1.0000x reference)
#include <cuda_runtime.h>
#include <math.h>

#define NN 50000
#define NFEAT 128
#define RDIM 128
#define NREL 500
#define NE 800000
#define NEN 100000
#define NET 900000
#define DOUT 128
#define ALPHA 0.2f

// output section offsets (floats)
#define OFF1 (NN*DOUT)            /* out_rel */
#define OFF2 (OFF1 + NREL*DOUT)   /* elu(h_num2) */
#define OFF3 (OFF2 + NN*DOUT)     /* elu(h_unif2) */

// ---------------- scratch (device globals; no allocation allowed) ----------------
static __device__ int  g_cnt[NN];
static __device__ int  g_rp[NN+1];
static __device__ int  g_cur[NN];
static __device__ int4 g_meta[NET];                       // (e1, idx, ta, tb)
static __device__ __align__(16) float2 g_ss1[NN];
static __device__ __align__(16) float2 g_sd1[NN];
static __device__ __align__(16) float g_cat1[(size_t)NN*512];   // [n][h][u1(128) u2(128)]
static __device__ __align__(16) float g_x2[(size_t)NN*128];
static __device__ float g_s2s[NN], g_s2d[NN];
static __device__ __align__(16) float g_acc2[(size_t)NN*512];   // [n][wx2 wor sx/c so/c]
static __device__ float g_rs2[NN];
static __device__ __align__(16) float g_pm2[(size_t)NN*128];
static __device__ __align__(16) float g_Y1[(size_t)NN*128];
static __device__ __align__(16) float g_Y2[(size_t)NN*128];
static __device__ __align__(16) float g_vvec[6][128];     // [h*3+w], w: 0=src 1=dst 2=rel
static __device__ __align__(8)  float g_srel1[2*NREL];    // [t*2+h]
static __device__ __align__(16) float g_w2[3][128];       // layer2: src,dst,rel fold vectors
static __device__ float g_s2rel[NREL];
static __device__ __align__(16) float g_outrel[NREL*128];
static __device__ __align__(16) float g_Bt1[2][384*64];   // a_heads transposed per head [k][o]
static __device__ __align__(16) float g_Bt2[384*128];     // a_out transposed [k][o]

// ---------------- helpers ----------------
__device__ __forceinline__ float lrelu(float z){ return z > 0.f ? z : ALPHA*z; }
__device__ __forceinline__ float eluf(float z){ return z > 0.f ? z : (expf(z) - 1.f); }
__device__ __forceinline__ float d4(float4 a, float4 b){
    return a.x*b.x + a.y*b.y + a.z*b.z + a.w*b.w;
}
__device__ __forceinline__ float wredsum(float v){
    #pragma unroll
    for (int o = 16; o; o >>= 1) v += __shfl_xor_sync(0xFFFFFFFFu, v, o);
    return v;
}

// ---------------- sort: histogram / scan / scatter ----------------
__global__ void k_zero(){
    int i = blockIdx.x*256 + threadIdx.x;
    if (i < NN) g_cnt[i] = 0;
}

__global__ void k_hist(const int* __restrict__ el, const int* __restrict__ eln){
    int i = blockIdx.x*256 + threadIdx.x;
    if (i >= NET) return;
    int n = (i < NE) ? el[i] : eln[i - NE];
    atomicAdd(&g_cnt[n], 1);
}

__global__ void k_scan(){
    __shared__ int sp[512];
    int t = threadIdx.x;
    const int C = (NN + 511) / 512;
    int base = t * C;
    int s = 0;
    for (int i = 0; i < C; i++){ int idx = base + i; if (idx < NN) s += g_cnt[idx]; }
    sp[t] = s; __syncthreads();
    for (int off = 1; off < 512; off <<= 1){
        int v = (t >= off) ? sp[t - off] : 0;
        __syncthreads();
        sp[t] += v;
        __syncthreads();
    }
    int pre = (t == 0) ? 0 : sp[t-1];
    for (int i = 0; i < C; i++){
        int idx = base + i;
        if (idx < NN){ g_rp[idx] = pre; g_cur[idx] = pre; pre += g_cnt[idx]; }
    }
    if (t == 511) g_rp[NN] = NET;
}

__global__ void k_scatter(const int* __restrict__ el, const int* __restrict__ et,
                          const int* __restrict__ eln, const int* __restrict__ etn){
    int i = blockIdx.x*256 + threadIdx.x;
    if (i >= NET) return;
    int n, e1, ta, tb;
    if (i < NE){
        n = el[i]; e1 = el[NE + i]; ta = et[i]; tb = -1;
    } else {
        int j = i - NE;
        n = eln[j]; e1 = eln[NEN + j]; ta = etn[2*j]; tb = etn[2*j + 1];
    }
    int pos = atomicAdd(&g_cur[n], 1);
    g_meta[pos] = make_int4(e1, i, ta, tb);
}

// ---------------- small precompute ----------------
__global__ void k_prep(const float* __restrict__ ah, const float* __restrict__ a2h,
                       const float* __restrict__ ao, const float* __restrict__ a2o){
    int id = blockIdx.x*256 + threadIdx.x;
    if (id < 49152){
        // Bt1[h][k*64+o] = a_heads[h][o][k]
        int h = id / 24576, r = id % 24576;
        int k = r / 64, o = r % 64;
        g_Bt1[h][r] = ah[h*24576 + o*384 + k];
    } else if (id < 98304){
        // Bt2[k*128+o] = a_out[o][k]
        int j = id - 49152;
        int k = j / 128, o = j % 128;
        g_Bt2[j] = ao[o*384 + k];
    } else if (id < 99072){
        // v vectors: v[h][w][k] = sum_o a2h[h][o]*a_heads[h][o][w*128+k]
        int j = id - 98304;
        int m = j / 128, k = j % 128;
        int h = m / 3, w = m % 3;
        float s = 0.f;
        #pragma unroll 4
        for (int o = 0; o < 64; o++)
            s += a2h[h*64 + o] * ah[h*24576 + o*384 + w*128 + k];
        g_vvec[m][k] = s;
    } else if (id < 99456){
        // w2[m][k] = sum_o a2o[o]*a_out[o][m*128+k]
        int j = id - 99072;
        int m = j / 128, k = j % 128;
        float s = 0.f;
        #pragma unroll 4
        for (int o = 0; o < 128; o++)
            s += a2o[o] * ao[o*384 + m*128 + k];
        g_w2[m][k] = s;
    }
}

__global__ void k_outrel(const float* __restrict__ rel, const float* __restrict__ W,
                         float* __restrict__ out){
    int id = blockIdx.x*256 + threadIdx.x;
    if (id >= NREL*128) return;
    int t = id / 128, o = id % 128;
    float s = 0.f;
    #pragma unroll 4
    for (int k = 0; k < 128; k++) s += rel[t*128 + k] * W[k*128 + o];
    g_outrel[id] = s;
    out[OFF1 + id] = s;
}

__global__ void k_srel(const float* __restrict__ rel){
    int id = blockIdx.x*256 + threadIdx.x;
    if (id < 1000){
        int t = id >> 1, h = id & 1;
        const float* v = g_vvec[h*3 + 2];
        float s = 0.f;
        #pragma unroll 4
        for (int k = 0; k < 128; k++) s += rel[t*128 + k] * v[k];
        g_srel1[id] = s;     // id == t*2 + h
    } else if (id < 1500){
        int t = id - 1000;
        float s = 0.f;
        #pragma unroll 4
        for (int k = 0; k < 128; k++) s += g_outrel[t*128 + k] * g_w2[2][k];
        g_s2rel[t] = s;
    }
}

// ---------------- per-node scalar dots ----------------
__global__ void k_sdots1(const float* __restrict__ x){
    int w = (blockIdx.x*blockDim.x + threadIdx.x) >> 5;
    int l = threadIdx.x & 31;
    if (w >= NN) return;
    float4 xv = ((const float4*)x)[w*32 + l];
    float p0 = d4(xv, ((const float4*)g_vvec[0])[l]);  // h0 src
    float p1 = d4(xv, ((const float4*)g_vvec[3])[l]);  // h1 src
    float p2 = d4(xv, ((const float4*)g_vvec[1])[l]);  // h0 dst
    float p3 = d4(xv, ((const float4*)g_vvec[4])[l]);  // h1 dst
    p0 = wredsum(p0); p1 = wredsum(p1); p2 = wredsum(p2); p3 = wredsum(p3);
    if (l == 0){
        g_ss1[w] = make_float2(p0, p1);
        g_sd1[w] = make_float2(p2, p3);
    }
}

__global__ void k_sdots2(){
    int w = (blockIdx.x*blockDim.x + threadIdx.x) >> 5;
    int l = threadIdx.x & 31;
    if (w >= NN) return;
    float4 xv = ((const float4*)g_x2)[w*32 + l];
    float p0 = d4(xv, ((const float4*)g_w2[0])[l]);
    float p1 = d4(xv, ((const float4*)g_w2[1])[l]);
    p0 = wredsum(p0); p1 = wredsum(p1);
    if (l == 0){ g_s2s[w] = p0; g_s2d[w] = p1; }
}

// ---------------- layer 1 edge pass (CSR, warp per node) ----------------
__global__ void k_edge1(const float* __restrict__ x, const float* __restrict__ eemb,
                        const float* __restrict__ rel){
    int w = (blockIdx.x*blockDim.x + threadIdx.x) >> 5;
    int l = threadIdx.x & 31;
    if (w >= NN) return;
    int beg = g_rp[w], end = g_rp[w+1];

    const float4* x4 = (const float4*)x;
    const float4* e4 = (const float4*)eemb;
    const float4* r4 = (const float4*)rel;
    float4 vr0 = ((const float4*)g_vvec[2])[l];   // h0 rel
    float4 vr1 = ((const float4*)g_vvec[5])[l];   // h1 rel
    float2 ssn = g_ss1[w];

    float4 wx0 = {0,0,0,0}, wx1 = {0,0,0,0}, we0 = {0,0,0,0}, we1 = {0,0,0,0};
    float rs0 = 0.f, rs1 = 0.f;

    for (int p = beg; p < end; p++){
        int4 mt = g_meta[p];
        int e1 = mt.x, idx = mt.y;
        float4 xv = x4[(size_t)e1*32 + l];
        float4 ev;
        float sr0, sr1;
        if (idx < NE){
            ev = e4[(size_t)idx*32 + l];
            float q0 = d4(ev, vr0);
            float q1 = d4(ev, vr1);
            #pragma unroll
            for (int o = 16; o; o >>= 1){
                q0 += __shfl_xor_sync(0xFFFFFFFFu, q0, o);
                q1 += __shfl_xor_sync(0xFFFFFFFFu, q1, o);
            }
            sr0 = q0; sr1 = q1;
        } else {
            int ta = mt.z, tb = mt.w;
            float4 ra = r4[ta*32 + l];
            float4 rb = r4[tb*32 + l];
            ev = make_float4(ra.x+rb.x, ra.y+rb.y, ra.z+rb.z, ra.w+rb.w);
            float2 sa = *(const float2*)(g_srel1 + ta*2);
            float2 sb = *(const float2*)(g_srel1 + tb*2);
            sr0 = sa.x + sb.x; sr1 = sa.y + sb.y;
        }
        float2 sd = g_sd1[e1];
        float z0 = ssn.x + sd.x + sr0;
        float z1 = ssn.y + sd.y + sr1;
        float ee0 = expf(-lrelu(z0));
        float ee1 = expf(-lrelu(z1));
        rs0 += ee0; rs1 += ee1;
        wx0.x += ee0*xv.x; wx0.y += ee0*xv.y; wx0.z += ee0*xv.z; wx0.w += ee0*xv.w;
        wx1.x += ee1*xv.x; wx1.y += ee1*xv.y; wx1.z += ee1*xv.z; wx1.w += ee1*xv.w;
        we0.x += ee0*ev.x; we0.y += ee0*ev.y; we0.z += ee0*ev.z; we0.w += ee0*ev.w;
        we1.x += ee1*ev.x; we1.y += ee1*ev.y; we1.z += ee1*ev.z; we1.w += ee1*ev.w;
    }
    float i0 = (end > beg) ? (1.f / rs0) : 0.f;
    float i1 = (end > beg) ? (1.f / rs1) : 0.f;
    float4* c4 = (float4*)g_cat1;
    size_t b = (size_t)w*128;
    c4[b +  0 + l] = make_float4(wx0.x*i0, wx0.y*i0, wx0.z*i0, wx0.w*i0);
    c4[b + 32 + l] = make_float4(we0.x*i0, we0.y*i0, we0.z*i0, we0.w*i0);
    c4[b + 64 + l] = make_float4(wx1.x*i1, wx1.y*i1, wx1.z*i1, wx1.w*i1);
    c4[b + 96 + l] = make_float4(we1.x*i1, we1.y*i1, we1.z*i1, we1.w*i1);
}

// ---------------- layer 2 edge pass ----------------
__global__ void k_edge2(){
    int w = (blockIdx.x*blockDim.x + threadIdx.x) >> 5;
    int l = threadIdx.x & 31;
    if (w >= NN) return;
    int beg = g_rp[w], end = g_rp[w+1];

    const float4* x4 = (const float4*)g_x2;
    const float4* o4 = (const float4*)g_outrel;
    float ssn = g_s2s[w];

    float4 wx = {0,0,0,0}, wo = {0,0,0,0}, sx = {0,0,0,0}, so = {0,0,0,0};
    float rs = 0.f;

    for (int p = beg; p < end; p++){
        int4 mt = g_meta[p];
        int e1 = mt.x, ta = mt.z, tb = mt.w;
        float4 xv = x4[(size_t)e1*32 + l];
        float4 ov;
        float sr;
        if (tb < 0){
            ov = o4[ta*32 + l];
            sr = g_s2rel[ta];
        } else {
            float4 ra = o4[ta*32 + l];
            float4 rb = o4[tb*32 + l];
            ov = make_float4(ra.x+rb.x, ra.y+rb.y, ra.z+rb.z, ra.w+rb.w);
            sr = g_s2rel[ta] + g_s2rel[tb];
        }
        float z = ssn + g_s2d[e1] + sr;
        float ee = expf(-lrelu(z));
        rs += ee;
        wx.x += ee*xv.x; wx.y += ee*xv.y; wx.z += ee*xv.z; wx.w += ee*xv.w;
        wo.x += ee*ov.x; wo.y += ee*ov.y; wo.z += ee*ov.z; wo.w += ee*ov.w;
        sx.x += xv.x; sx.y += xv.y; sx.z += xv.z; sx.w += xv.w;
        so.x += ov.x; so.y += ov.y; so.z += ov.z; so.w += ov.w;
    }
    int cnt = end - beg;
    float ic = cnt ? (1.f / (float)cnt) : 0.f;
    float4* a4 = (float4*)g_acc2;
    size_t b = (size_t)w*128;
    a4[b +  0 + l] = wx;
    a4[b + 32 + l] = wo;
    a4[b + 64 + l] = make_float4(sx.x*ic, sx.y*ic, sx.z*ic, sx.w*ic);
    a4[b + 96 + l] = make_float4(so.x*ic, so.y*ic, so.z*ic, so.w*ic);
    if (l == 0) g_rs2[w] = rs;
}

// ---------------- generic fp32 tiled GEMM (128 x BN, BK=16, 8xTN microtile) ----------------
template<int BN, int TN>
__global__ __launch_bounds__(256) void k_gemm(int which, const float* __restrict__ Aext){
    const int BM = 128, BK = 16, TM = 8;
    const float *A1, *A2, *Bt;
    float* C;
    int lda1, lda2, K1, K, ldb, ldc, coff, mode;
    if (BN == 64){
        int h = which;
        A1 = Aext; lda1 = 128;
        A2 = g_cat1 + h*256; lda2 = 512;
        K1 = 128; K = 384;
        Bt = g_Bt1[h]; ldb = 64;
        C = g_x2; ldc = 128; coff = h*64; mode = 1;
    } else {
        if (which == 2){
            A1 = g_x2; lda1 = 128; A2 = 0; lda2 = 0; K1 = 128; K = 128;
            Bt = g_Bt2; ldb = 128; C = g_pm2;
        } else if (which == 3){
            A1 = g_acc2; lda1 = 512; A2 = 0; lda2 = 0; K1 = 256; K = 256;
            Bt = g_Bt2 + 128*128; ldb = 128; C = g_Y1;
        } else {
            A1 = g_acc2 + 256; lda1 = 512; A2 = 0; lda2 = 0; K1 = 256; K = 256;
            Bt = g_Bt2 + 128*128; ldb = 128; C = g_Y2;
        }
        ldc = 128; coff = 0; mode = 0;
    }
    const int M = NN;

    __shared__ float As[BK][BM + 1];
    __shared__ float Bs[BK][BN];
    int tid = threadIdx.x;
    int bm0 = blockIdx.x * BM;
    int tr = tid / 16;       // 0..15 -> rows tr*8..tr*8+7
    int tc = tid % 16;       // 0..15 -> cols tc*TN..
    int rA = tid >> 2;       // 0..63
    int kA = (tid & 3) * 4;

    float acc[TM][TN];
    #pragma unroll
    for (int i = 0; i < TM; i++)
        #pragma unroll
        for (int j = 0; j < TN; j++) acc[i][j] = 0.f;

    for (int k0 = 0; k0 < K; k0 += BK){
        const float* Ab; int ldA, kl;
        if (k0 < K1){ Ab = A1; ldA = lda1; kl = k0; }
        else        { Ab = A2; ldA = lda2; kl = k0 - K1; }
        #pragma unroll
        for (int rr = 0; rr < 2; rr++){
            int m = bm0 + rA + rr*64;
            float4 v = make_float4(0,0,0,0);
            if (m < M) v = *(const float4*)(Ab + (size_t)m*ldA + kl + kA);
            As[kA+0][rA + rr*64] = v.x;
            As[kA+1][rA + rr*64] = v.y;
            As[kA+2][rA + rr*64] = v.z;
            As[kA+3][rA + rr*64] = v.w;
        }
        if (BN == 128){
            #pragma unroll
            for (int rr = 0; rr < 2; rr++){
                int kk = (tid >> 5) + rr*8, oo = (tid & 31)*4;
                *(float4*)&Bs[kk][oo] = *(const float4*)(Bt + (size_t)(k0+kk)*ldb + oo);
            }
        } else {
            int kk = tid >> 4, oo = (tid & 15)*4;
            *(float4*)&Bs[kk][oo] = *(const float4*)(Bt + (size_t)(k0+kk)*ldb + oo);
        }
        __syncthreads();
        #pragma unroll
        for (int k = 0; k < BK; k++){
            float a[TM], b[TN];
            #pragma unroll
            for (int i = 0; i < TM; i++) a[i] = As[k][tr*TM + i];
            #pragma unroll
            for (int j = 0; j < TN; j++) b[j] = Bs[k][tc*TN + j];
            #pragma unroll
            for (int i = 0; i < TM; i++)
                #pragma unroll
                for (int j = 0; j < TN; j++) acc[i][j] += a[i]*b[j];
        }
        __syncthreads();
    }
    #pragma unroll
    for (int i = 0; i < TM; i++){
        int m = bm0 + tr*TM + i;
        if (m >= M) continue;
        bool live = true;
        if (mode == 1) live = (g_rp[m+1] - g_rp[m]) > 0;
        #pragma unroll
        for (int j = 0; j < TN; j++){
            float v = acc[i][j];
            if (mode == 1) v = live ? eluf(v) : 0.f;
            C[(size_t)m*ldc + coff + tc*TN + j] = v;
        }
    }
}

// ---------------- final epilogue ----------------
__global__ void k_final(float* __restrict__ out){
    int id = blockIdx.x*256 + threadIdx.x;
    if (id >= NN*32) return;
    int n = id >> 5, l = id & 31;
    int cnt = g_rp[n+1] - g_rp[n];
    float4 o0 = {0,0,0,0}, o2 = {0,0,0,0}, o3 = {0,0,0,0};
    if (cnt > 0){
        float rs = g_rs2[n];
        float inv = 1.f / rs;
        float4 pm = ((const float4*)g_pm2)[(size_t)n*32 + l];
        float4 y1 = ((const float4*)g_Y1 )[(size_t)n*32 + l];
        float4 y2 = ((const float4*)g_Y2 )[(size_t)n*32 + l];
        float4 hn = make_float4(rs*pm.x + y1.x, rs*pm.y + y1.y,
                                rs*pm.z + y1.z, rs*pm.w + y1.w);
        float4 h  = make_float4(hn.x*inv, hn.y*inv, hn.z*inv, hn.w*inv);
        float4 un = make_float4(pm.x + y2.x, pm.y + y2.y, pm.z + y2.z, pm.w + y2.w);
        o0 = make_float4(eluf(h.x),  eluf(h.y),  eluf(h.z),  eluf(h.w));
        o2 = make_float4(eluf(hn.x), eluf(hn.y), eluf(hn.z), eluf(hn.w));
        o3 = make_float4(eluf(un.x), eluf(un.y), eluf(un.z), eluf(un.w));
    }
    float4* out4 = (float4*)out;
    out4[(size_t)n*32 + l]                 = o0;
    out4[(size_t)(OFF2/4) + n*32 + l]      = o2;
    out4[(size_t)(OFF3/4) + n*32 + l]      = o3;
}

// ---------------- launcher ----------------
extern "C" void kernel_launch(void* const* d_in, const int* in_sizes, int n_in,
                              void* d_out, int out_size){
    const float* x    = (const float*)d_in[0];
    const float* rel  = (const float*)d_in[1];
    const float* eemb = (const float*)d_in[2];
    const float* ah   = (const float*)d_in[3];
    const float* a2h  = (const float*)d_in[4];
    const float* W    = (const float*)d_in[5];
    const float* ao   = (const float*)d_in[6];
    const float* a2o  = (const float*)d_in[7];
    const int* el  = (const int*)d_in[8];
    const int* et  = (const int*)d_in[9];
    const int* eln = (const int*)d_in[10];
    const int* etn = (const int*)d_in[11];
    float* out = (float*)d_out;

    // CSR build
    k_zero<<<(NN + 255)/256, 256>>>();
    k_hist<<<(NET + 255)/256, 256>>>(el, eln);
    k_scan<<<1, 512>>>();
    k_scatter<<<(NET + 255)/256, 256>>>(el, et, eln, etn);

    // small precompute
    k_prep<<<(99456 + 255)/256, 256>>>(ah, a2h, ao, a2o);
    k_outrel<<<(NREL*128 + 255)/256, 256>>>(rel, W, out);
    k_srel<<<(1500 + 255)/256, 256>>>(rel);

    // layer 1
    k_sdots1<<<6250, 256>>>(x);
    k_edge1<<<6250, 256>>>(x, eemb, rel);
    k_gemm<64,4><<<(NN + 127)/128, 256>>>(0, x);
    k_gemm<64,4><<<(NN + 127)/128, 256>>>(1, x);

    // layer 2
    k_sdots2<<<6250, 256>>>();
    k_edge2<<<6250, 256>>>();
    k_gemm<128,8><<<(NN + 127)/128, 256>>>(2, x);
    k_gemm<128,8><<<(NN + 127)/128, 256>>>(3, x);
    k_gemm<128,8><<<(NN + 127)/128, 256>>>(4, x);

    k_final<<<(NN*32 + 255)/256, 256>>>(out);
}

// round 4
// speedup vs baseline: 1.2000x; 1.2000x over previous
#include <cuda_runtime.h>
#include <cuda_bf16.h>
#include <math.h>

#define NN 50000
#define NFEAT 128
#define RDIM 128
#define NREL 500
#define NE 800000
#define NEN 100000
#define NET 900000
#define DOUT 128
#define ALPHA 0.2f

// output section offsets (floats)
#define OFF1 (NN*DOUT)            /* out_rel */
#define OFF2 (OFF1 + NREL*DOUT)   /* elu(h_num2) */
#define OFF3 (OFF2 + NN*DOUT)     /* elu(h_unif2) */

// ---------------- scratch (device globals; no allocation allowed) ----------------
static __device__ int  g_cnt[NN];
static __device__ int  g_rp[NN+1];
static __device__ int  g_cur[NN];
static __device__ int4 g_meta[NET];                       // (e1, idx, ta, tb)
static __device__ __align__(16) float2 g_ss1[NN];
static __device__ __align__(16) float2 g_sd1[NN];
static __device__ __align__(16) float g_cat1[(size_t)NN*512];   // [n][h][u1(128) u2(128)]
static __device__ __align__(16) float g_x2[(size_t)NN*128];
static __device__ float g_s2s[NN], g_s2d[NN];
static __device__ __align__(16) float g_acc2[(size_t)NN*512];   // [n][wx2 wor sx/c so/c]
static __device__ float g_rs2[NN];
static __device__ __align__(16) float g_pm2[(size_t)NN*128];
static __device__ __align__(16) float g_Y1[(size_t)NN*128];
static __device__ __align__(16) float g_Y2[(size_t)NN*128];
static __device__ __align__(16) float g_vvec[6][128];     // [h*3+w], w: 0=src 1=dst 2=rel
static __device__ __align__(8)  float g_srel1[2*NREL];    // [t*2+h]
static __device__ __align__(16) float g_w2[3][128];       // layer2: src,dst,rel fold vectors
static __device__ float g_s2rel[NREL];
static __device__ __align__(16) float g_outrel[NREL*128];
// bf16 hi/lo weights in ORIGINAL [o][k] layout (k contiguous) — matches mma row.col B
static __device__ __align__(16) __nv_bfloat16 g_Bh1[2*64*384];
static __device__ __align__(16) __nv_bfloat16 g_Bl1[2*64*384];
static __device__ __align__(16) __nv_bfloat16 g_Bh2[128*384];
static __device__ __align__(16) __nv_bfloat16 g_Bl2[128*384];

// ---------------- helpers ----------------
__device__ __forceinline__ float lrelu(float z){ return z > 0.f ? z : ALPHA*z; }
__device__ __forceinline__ float eluf(float z){ return z > 0.f ? z : (expf(z) - 1.f); }
__device__ __forceinline__ float d4(float4 a, float4 b){
    return a.x*b.x + a.y*b.y + a.z*b.z + a.w*b.w;
}
__device__ __forceinline__ float wredsum(float v){
    #pragma unroll
    for (int o = 16; o; o >>= 1) v += __shfl_xor_sync(0xFFFFFFFFu, v, o);
    return v;
}
__device__ __forceinline__ unsigned smem_u32(const void* p){
    return (unsigned)__cvta_generic_to_shared(p);
}
__device__ __forceinline__ void ldsm4(unsigned &r0, unsigned &r1, unsigned &r2, unsigned &r3, unsigned a){
    asm volatile("ldmatrix.sync.aligned.m8n8.x4.shared.b16 {%0,%1,%2,%3},[%4];"
        : "=r"(r0),"=r"(r1),"=r"(r2),"=r"(r3) : "r"(a));
}
__device__ __forceinline__ void mmabf(float* d, const unsigned* a, const unsigned* b){
    asm volatile("mma.sync.aligned.m16n8k16.row.col.f32.bf16.bf16.f32 "
        "{%0,%1,%2,%3},{%4,%5,%6,%7},{%8,%9},{%0,%1,%2,%3};"
        : "+f"(d[0]),"+f"(d[1]),"+f"(d[2]),"+f"(d[3])
        : "r"(a[0]),"r"(a[1]),"r"(a[2]),"r"(a[3]),"r"(b[0]),"r"(b[1]));
}

// ---------------- sort: histogram / scan / scatter ----------------
__global__ void k_zero(){
    int i = blockIdx.x*256 + threadIdx.x;
    if (i < NN) g_cnt[i] = 0;
}

__global__ void k_hist(const int* __restrict__ el, const int* __restrict__ eln){
    int i = blockIdx.x*256 + threadIdx.x;
    if (i >= NET) return;
    int n = (i < NE) ? el[i] : eln[i - NE];
    atomicAdd(&g_cnt[n], 1);
}

__global__ void k_scan(){
    __shared__ int sp[512];
    int t = threadIdx.x;
    const int C = (NN + 511) / 512;
    int base = t * C;
    int s = 0;
    for (int i = 0; i < C; i++){ int idx = base + i; if (idx < NN) s += g_cnt[idx]; }
    sp[t] = s; __syncthreads();
    for (int off = 1; off < 512; off <<= 1){
        int v = (t >= off) ? sp[t - off] : 0;
        __syncthreads();
        sp[t] += v;
        __syncthreads();
    }
    int pre = (t == 0) ? 0 : sp[t-1];
    for (int i = 0; i < C; i++){
        int idx = base + i;
        if (idx < NN){ g_rp[idx] = pre; g_cur[idx] = pre; pre += g_cnt[idx]; }
    }
    if (t == 511) g_rp[NN] = NET;
}

__global__ void k_scatter(const int* __restrict__ el, const int* __restrict__ et,
                          const int* __restrict__ eln, const int* __restrict__ etn){
    int i = blockIdx.x*256 + threadIdx.x;
    if (i >= NET) return;
    int n, e1, ta, tb;
    if (i < NE){
        n = el[i]; e1 = el[NE + i]; ta = et[i]; tb = -1;
    } else {
        int j = i - NE;
        n = eln[j]; e1 = eln[NEN + j]; ta = etn[2*j]; tb = etn[2*j + 1];
    }
    int pos = atomicAdd(&g_cur[n], 1);
    g_meta[pos] = make_int4(e1, i, ta, tb);
}

// ---------------- small precompute ----------------
__global__ void k_prep(const float* __restrict__ ah, const float* __restrict__ a2h,
                       const float* __restrict__ ao, const float* __restrict__ a2o){
    int id = blockIdx.x*256 + threadIdx.x;
    if (id < 49152){
        // bf16 hi/lo of a_heads, kept in [h][o][k] layout
        float v = ah[id];
        __nv_bfloat16 h = __float2bfloat16(v);
        g_Bh1[id] = h;
        g_Bl1[id] = __float2bfloat16(v - __bfloat162float(h));
    } else if (id < 98304){
        int j = id - 49152;
        float v = ao[j];
        __nv_bfloat16 h = __float2bfloat16(v);
        g_Bh2[j] = h;
        g_Bl2[j] = __float2bfloat16(v - __bfloat162float(h));
    } else if (id < 99072){
        // v vectors: v[h][w][k] = sum_o a2h[h][o]*a_heads[h][o][w*128+k]
        int j = id - 98304;
        int m = j / 128, k = j % 128;
        int h = m / 3, w = m % 3;
        float s = 0.f;
        #pragma unroll 4
        for (int o = 0; o < 64; o++)
            s += a2h[h*64 + o] * ah[h*24576 + o*384 + w*128 + k];
        g_vvec[m][k] = s;
    } else if (id < 99456){
        // w2[m][k] = sum_o a2o[o]*a_out[o][m*128+k]
        int j = id - 99072;
        int m = j / 128, k = j % 128;
        float s = 0.f;
        #pragma unroll 4
        for (int o = 0; o < 128; o++)
            s += a2o[o] * ao[o*384 + m*128 + k];
        g_w2[m][k] = s;
    }
}

__global__ void k_outrel(const float* __restrict__ rel, const float* __restrict__ W,
                         float* __restrict__ out){
    int id = blockIdx.x*256 + threadIdx.x;
    if (id >= NREL*128) return;
    int t = id / 128, o = id % 128;
    float s = 0.f;
    #pragma unroll 4
    for (int k = 0; k < 128; k++) s += rel[t*128 + k] * W[k*128 + o];
    g_outrel[id] = s;
    out[OFF1 + id] = s;
}

__global__ void k_srel(const float* __restrict__ rel){
    int id = blockIdx.x*256 + threadIdx.x;
    if (id < 1000){
        int t = id >> 1, h = id & 1;
        const float* v = g_vvec[h*3 + 2];
        float s = 0.f;
        #pragma unroll 4
        for (int k = 0; k < 128; k++) s += rel[t*128 + k] * v[k];
        g_srel1[id] = s;     // id == t*2 + h
    } else if (id < 1500){
        int t = id - 1000;
        float s = 0.f;
        #pragma unroll 4
        for (int k = 0; k < 128; k++) s += g_outrel[t*128 + k] * g_w2[2][k];
        g_s2rel[t] = s;
    }
}

// ---------------- per-node scalar dots ----------------
__global__ void k_sdots1(const float* __restrict__ x){
    int w = (blockIdx.x*blockDim.x + threadIdx.x) >> 5;
    int l = threadIdx.x & 31;
    if (w >= NN) return;
    float4 xv = ((const float4*)x)[w*32 + l];
    float p0 = d4(xv, ((const float4*)g_vvec[0])[l]);  // h0 src
    float p1 = d4(xv, ((const float4*)g_vvec[3])[l]);  // h1 src
    float p2 = d4(xv, ((const float4*)g_vvec[1])[l]);  // h0 dst
    float p3 = d4(xv, ((const float4*)g_vvec[4])[l]);  // h1 dst
    p0 = wredsum(p0); p1 = wredsum(p1); p2 = wredsum(p2); p3 = wredsum(p3);
    if (l == 0){
        g_ss1[w] = make_float2(p0, p1);
        g_sd1[w] = make_float2(p2, p3);
    }
}

__global__ void k_sdots2(){
    int w = (blockIdx.x*blockDim.x + threadIdx.x) >> 5;
    int l = threadIdx.x & 31;
    if (w >= NN) return;
    float4 xv = ((const float4*)g_x2)[w*32 + l];
    float p0 = d4(xv, ((const float4*)g_w2[0])[l]);
    float p1 = d4(xv, ((const float4*)g_w2[1])[l]);
    p0 = wredsum(p0); p1 = wredsum(p1);
    if (l == 0){ g_s2s[w] = p0; g_s2d[w] = p1; }
}

// ---------------- layer 1 edge pass (CSR, warp per node) ----------------
__global__ void k_edge1(const float* __restrict__ x, const float* __restrict__ eemb,
                        const float* __restrict__ rel){
    int w = (blockIdx.x*blockDim.x + threadIdx.x) >> 5;
    int l = threadIdx.x & 31;
    if (w >= NN) return;
    int beg = g_rp[w], end = g_rp[w+1];

    const float4* x4 = (const float4*)x;
    const float4* e4 = (const float4*)eemb;
    const float4* r4 = (const float4*)rel;
    float4 vr0 = ((const float4*)g_vvec[2])[l];   // h0 rel
    float4 vr1 = ((const float4*)g_vvec[5])[l];   // h1 rel
    float2 ssn = g_ss1[w];

    float4 wx0 = {0,0,0,0}, wx1 = {0,0,0,0}, we0 = {0,0,0,0}, we1 = {0,0,0,0};
    float rs0 = 0.f, rs1 = 0.f;

    for (int p = beg; p < end; p++){
        int4 mt = g_meta[p];
        int e1 = mt.x, idx = mt.y;
        float4 xv = x4[(size_t)e1*32 + l];
        float4 ev;
        float sr0, sr1;
        if (idx < NE){
            ev = e4[(size_t)idx*32 + l];
            float q0 = d4(ev, vr0);
            float q1 = d4(ev, vr1);
            #pragma unroll
            for (int o = 16; o; o >>= 1){
                q0 += __shfl_xor_sync(0xFFFFFFFFu, q0, o);
                q1 += __shfl_xor_sync(0xFFFFFFFFu, q1, o);
            }
            sr0 = q0; sr1 = q1;
        } else {
            int ta = mt.z, tb = mt.w;
            float4 ra = r4[ta*32 + l];
            float4 rb = r4[tb*32 + l];
            ev = make_float4(ra.x+rb.x, ra.y+rb.y, ra.z+rb.z, ra.w+rb.w);
            float2 sa = *(const float2*)(g_srel1 + ta*2);
            float2 sb = *(const float2*)(g_srel1 + tb*2);
            sr0 = sa.x + sb.x; sr1 = sa.y + sb.y;
        }
        float2 sd = g_sd1[e1];
        float z0 = ssn.x + sd.x + sr0;
        float z1 = ssn.y + sd.y + sr1;
        float ee0 = expf(-lrelu(z0));
        float ee1 = expf(-lrelu(z1));
        rs0 += ee0; rs1 += ee1;
        wx0.x += ee0*xv.x; wx0.y += ee0*xv.y; wx0.z += ee0*xv.z; wx0.w += ee0*xv.w;
        wx1.x += ee1*xv.x; wx1.y += ee1*xv.y; wx1.z += ee1*xv.z; wx1.w += ee1*xv.w;
        we0.x += ee0*ev.x; we0.y += ee0*ev.y; we0.z += ee0*ev.z; we0.w += ee0*ev.w;
        we1.x += ee1*ev.x; we1.y += ee1*ev.y; we1.z += ee1*ev.z; we1.w += ee1*ev.w;
    }
    float i0 = (end > beg) ? (1.f / rs0) : 0.f;
    float i1 = (end > beg) ? (1.f / rs1) : 0.f;
    float4* c4 = (float4*)g_cat1;
    size_t b = (size_t)w*128;
    c4[b +  0 + l] = make_float4(wx0.x*i0, wx0.y*i0, wx0.z*i0, wx0.w*i0);
    c4[b + 32 + l] = make_float4(we0.x*i0, we0.y*i0, we0.z*i0, we0.w*i0);
    c4[b + 64 + l] = make_float4(wx1.x*i1, wx1.y*i1, wx1.z*i1, wx1.w*i1);
    c4[b + 96 + l] = make_float4(we1.x*i1, we1.y*i1, we1.z*i1, we1.w*i1);
}

// ---------------- layer 2 edge pass ----------------
__global__ void k_edge2(){
    int w = (blockIdx.x*blockDim.x + threadIdx.x) >> 5;
    int l = threadIdx.x & 31;
    if (w >= NN) return;
    int beg = g_rp[w], end = g_rp[w+1];

    const float4* x4 = (const float4*)g_x2;
    const float4* o4 = (const float4*)g_outrel;
    float ssn = g_s2s[w];

    float4 wx = {0,0,0,0}, wo = {0,0,0,0}, sx = {0,0,0,0}, so = {0,0,0,0};
    float rs = 0.f;

    for (int p = beg; p < end; p++){
        int4 mt = g_meta[p];
        int e1 = mt.x, ta = mt.z, tb = mt.w;
        float4 xv = x4[(size_t)e1*32 + l];
        float4 ov;
        float sr;
        if (tb < 0){
            ov = o4[ta*32 + l];
            sr = g_s2rel[ta];
        } else {
            float4 ra = o4[ta*32 + l];
            float4 rb = o4[tb*32 + l];
            ov = make_float4(ra.x+rb.x, ra.y+rb.y, ra.z+rb.z, ra.w+rb.w);
            sr = g_s2rel[ta] + g_s2rel[tb];
        }
        float z = ssn + g_s2d[e1] + sr;
        float ee = expf(-lrelu(z));
        rs += ee;
        wx.x += ee*xv.x; wx.y += ee*xv.y; wx.z += ee*xv.z; wx.w += ee*xv.w;
        wo.x += ee*ov.x; wo.y += ee*ov.y; wo.z += ee*ov.z; wo.w += ee*ov.w;
        sx.x += xv.x; sx.y += xv.y; sx.z += xv.z; sx.w += xv.w;
        so.x += ov.x; so.y += ov.y; so.z += ov.z; so.w += ov.w;
    }
    int cnt = end - beg;
    float ic = cnt ? (1.f / (float)cnt) : 0.f;
    float4* a4 = (float4*)g_acc2;
    size_t b = (size_t)w*128;
    a4[b +  0 + l] = wx;
    a4[b + 32 + l] = wo;
    a4[b + 64 + l] = make_float4(sx.x*ic, sx.y*ic, sx.z*ic, sx.w*ic);
    a4[b + 96 + l] = make_float4(so.x*ic, so.y*ic, so.z*ic, so.w*ic);
    if (l == 0) g_rs2[w] = rs;
}

// ---------------- tensor-core GEMM (bf16x3 split, fp32 accuracy) ----------------
// C[m][n] = sum_k A[m][k]*B[n][k]   (B given as bf16 hi/lo in [n][k] layout, ldb=384)
// which: 0/1 -> layer1 heads (BN=64), 2 -> pm2, 3 -> Y1, 4 -> Y2 (BN=128)
template<int BN>
__global__ __launch_bounds__(256) void k_tgemm(int base, const float* __restrict__ Aext){
    const int which = base + blockIdx.y;
    const float *A1, *A2;
    const __nv_bfloat16 *Bh, *Bl;
    float* C;
    int lda1, lda2, K1, K, kB0, coff, mode;
    if (BN == 64){
        int h = which;
        A1 = Aext; lda1 = 128;
        A2 = g_cat1 + h*256; lda2 = 512;
        K1 = 128; K = 384;
        Bh = g_Bh1 + h*24576; Bl = g_Bl1 + h*24576; kB0 = 0;
        C = g_x2; coff = h*64; mode = 1;
    } else if (which == 2){
        A1 = g_x2; lda1 = 128; A2 = g_x2; lda2 = 128; K1 = 128; K = 128;
        Bh = g_Bh2; Bl = g_Bl2; kB0 = 0;
        C = g_pm2; coff = 0; mode = 0;
    } else if (which == 3){
        A1 = g_acc2; lda1 = 512; A2 = g_acc2; lda2 = 512; K1 = 256; K = 256;
        Bh = g_Bh2; Bl = g_Bl2; kB0 = 128;
        C = g_Y1; coff = 0; mode = 0;
    } else {
        A1 = g_acc2 + 256; lda1 = 512; A2 = g_acc2 + 256; lda2 = 512; K1 = 256; K = 256;
        Bh = g_Bh2; Bl = g_Bl2; kB0 = 128;
        C = g_Y2; coff = 0; mode = 0;
    }
    const int ldc = 128, M = NN;
    constexpr int NF = BN / 16;

    __shared__ __align__(16) __nv_bfloat16 Ah[128][40];
    __shared__ __align__(16) __nv_bfloat16 Al[128][40];
    __shared__ __align__(16) __nv_bfloat16 Bhs[BN][40];
    __shared__ __align__(16) __nv_bfloat16 Bls[BN][40];

    int tid = threadIdx.x, lane = tid & 31, warp = tid >> 5;
    int wm = (warp & 3) * 32;
    int wn = (warp >> 2) * (BN/2);
    int bm0 = blockIdx.x * 128;

    float d[2][NF][4];
    #pragma unroll
    for (int f = 0; f < 2; f++)
        #pragma unroll
        for (int j = 0; j < NF; j++)
            #pragma unroll
            for (int q = 0; q < 4; q++) d[f][j][q] = 0.f;

    int ar = tid >> 1, akq = (tid & 1) * 16;
    constexpr int tpr = 256 / BN;              // threads per B row: 2 or 4
    int bn = tid / tpr;
    int bkq = (tid % tpr) * (32 / tpr);

    for (int k0 = 0; k0 < K; k0 += 32){
        // ---- A tile (fp32 -> bf16 hi/lo) ----
        const float* Ab; int ldA, kl;
        if (k0 < K1){ Ab = A1; ldA = lda1; kl = k0; }
        else        { Ab = A2; ldA = lda2; kl = k0 - K1; }
        int m = bm0 + ar;
        bool mv = m < M;
        const float* asrc = Ab + (size_t)m*ldA + kl + akq;
        #pragma unroll
        for (int j = 0; j < 16; j += 4){
            float4 v = mv ? *(const float4*)(asrc + j) : make_float4(0,0,0,0);
            __nv_bfloat162 h0 = __floats2bfloat162_rn(v.x, v.y);
            __nv_bfloat162 h1 = __floats2bfloat162_rn(v.z, v.w);
            __nv_bfloat162 l0 = __floats2bfloat162_rn(v.x - __low2float(h0),
                                                      v.y - __high2float(h0));
            __nv_bfloat162 l1 = __floats2bfloat162_rn(v.z - __low2float(h1),
                                                      v.w - __high2float(h1));
            *(__nv_bfloat162*)&Ah[ar][akq+j]   = h0;
            *(__nv_bfloat162*)&Ah[ar][akq+j+2] = h1;
            *(__nv_bfloat162*)&Al[ar][akq+j]   = l0;
            *(__nv_bfloat162*)&Al[ar][akq+j+2] = l1;
        }
        // ---- B tile (bf16 copy) ----
        const __nv_bfloat16* bsH = Bh + (size_t)bn*384 + kB0 + k0 + bkq;
        const __nv_bfloat16* bsL = Bl + (size_t)bn*384 + kB0 + k0 + bkq;
        #pragma unroll
        for (int j = 0; j < 32/tpr; j += 8){
            *(uint4*)&Bhs[bn][bkq+j] = *(const uint4*)(bsH + j);
            *(uint4*)&Bls[bn][bkq+j] = *(const uint4*)(bsL + j);
        }
        __syncthreads();

        #pragma unroll
        for (int kk = 0; kk < 32; kk += 16){
            unsigned ah_[2][4], al_[2][4], bh_[NF][2], bl_[NF][2];
            #pragma unroll
            for (int f = 0; f < 2; f++){
                int rrow = wm + f*16 + (lane & 15);
                int rcol = kk + (lane >> 4) * 8;
                ldsm4(ah_[f][0], ah_[f][1], ah_[f][2], ah_[f][3],
                      smem_u32(&Ah[rrow][rcol]));
                ldsm4(al_[f][0], al_[f][1], al_[f][2], al_[f][3],
                      smem_u32(&Al[rrow][rcol]));
            }
            #pragma unroll
            for (int g = 0; g < NF/2; g++){
                int nb = wn + g*16 + ((lane >> 4) << 3) + (lane & 7);
                int kc = kk + ((lane >> 3) & 1) * 8;
                ldsm4(bh_[2*g][0], bh_[2*g][1], bh_[2*g+1][0], bh_[2*g+1][1],
                      smem_u32(&Bhs[nb][kc]));
                ldsm4(bl_[2*g][0], bl_[2*g][1], bl_[2*g+1][0], bl_[2*g+1][1],
                      smem_u32(&Bls[nb][kc]));
            }
            #pragma unroll
            for (int f = 0; f < 2; f++)
                #pragma unroll
                for (int j = 0; j < NF; j++){
                    mmabf(d[f][j], ah_[f], bh_[j]);
                    mmabf(d[f][j], ah_[f], bl_[j]);
                    mmabf(d[f][j], al_[f], bh_[j]);
                }
        }
        __syncthreads();
    }

    // ---- epilogue ----
    int gid = lane >> 2, tig = lane & 3;
    #pragma unroll
    for (int f = 0; f < 2; f++){
        #pragma unroll
        for (int j = 0; j < NF; j++){
            int col = coff + wn + j*8 + tig*2;
            int m0r = bm0 + wm + f*16 + gid;
            #pragma unroll
            for (int half = 0; half < 2; half++){
                int m = m0r + half*8;
                if (m >= M) continue;
                float v0 = d[f][j][half*2+0];
                float v1 = d[f][j][half*2+1];
                if (mode == 1){
                    bool live = (g_rp[m+1] - g_rp[m]) > 0;
                    v0 = live ? eluf(v0) : 0.f;
                    v1 = live ? eluf(v1) : 0.f;
                }
                *(float2*)&C[(size_t)m*ldc + col] = make_float2(v0, v1);
            }
        }
    }
}

// ---------------- final epilogue ----------------
__global__ void k_final(float* __restrict__ out){
    int id = blockIdx.x*256 + threadIdx.x;
    if (id >= NN*32) return;
    int n = id >> 5, l = id & 31;
    int cnt = g_rp[n+1] - g_rp[n];
    float4 o0 = {0,0,0,0}, o2 = {0,0,0,0}, o3 = {0,0,0,0};
    if (cnt > 0){
        float rs = g_rs2[n];
        float inv = 1.f / rs;
        float4 pm = ((const float4*)g_pm2)[(size_t)n*32 + l];
        float4 y1 = ((const float4*)g_Y1 )[(size_t)n*32 + l];
        float4 y2 = ((const float4*)g_Y2 )[(size_t)n*32 + l];
        float4 hn = make_float4(rs*pm.x + y1.x, rs*pm.y + y1.y,
                                rs*pm.z + y1.z, rs*pm.w + y1.w);
        float4 h  = make_float4(hn.x*inv, hn.y*inv, hn.z*inv, hn.w*inv);
        float4 un = make_float4(pm.x + y2.x, pm.y + y2.y, pm.z + y2.z, pm.w + y2.w);
        o0 = make_float4(eluf(h.x),  eluf(h.y),  eluf(h.z),  eluf(h.w));
        o2 = make_float4(eluf(hn.x), eluf(hn.y), eluf(hn.z), eluf(hn.w));
        o3 = make_float4(eluf(un.x), eluf(un.y), eluf(un.z), eluf(un.w));
    }
    float4* out4 = (float4*)out;
    out4[(size_t)n*32 + l]                 = o0;
    out4[(size_t)(OFF2/4) + n*32 + l]      = o2;
    out4[(size_t)(OFF3/4) + n*32 + l]      = o3;
}

// ---------------- launcher ----------------
extern "C" void kernel_launch(void* const* d_in, const int* in_sizes, int n_in,
                              void* d_out, int out_size){
    const float* x    = (const float*)d_in[0];
    const float* rel  = (const float*)d_in[1];
    const float* eemb = (const float*)d_in[2];
    const float* ah   = (const float*)d_in[3];
    const float* a2h  = (const float*)d_in[4];
    const float* W    = (const float*)d_in[5];
    const float* ao   = (const float*)d_in[6];
    const float* a2o  = (const float*)d_in[7];
    const int* el  = (const int*)d_in[8];
    const int* et  = (const int*)d_in[9];
    const int* eln = (const int*)d_in[10];
    const int* etn = (const int*)d_in[11];
    float* out = (float*)d_out;

    const int GB = (NN + 127) / 128;   // 391

    // CSR build
    k_zero<<<(NN + 255)/256, 256>>>();
    k_hist<<<(NET + 255)/256, 256>>>(el, eln);
    k_scan<<<1, 512>>>();
    k_scatter<<<(NET + 255)/256, 256>>>(el, et, eln, etn);

    // small precompute
    k_prep<<<(99456 + 255)/256, 256>>>(ah, a2h, ao, a2o);
    k_outrel<<<(NREL*128 + 255)/256, 256>>>(rel, W, out);
    k_srel<<<(1500 + 255)/256, 256>>>(rel);

    // layer 1
    k_sdots1<<<6250, 256>>>(x);
    k_edge1<<<6250, 256>>>(x, eemb, rel);
    k_tgemm<64><<<dim3(GB, 2), 256>>>(0, x);     // heads 0 & 1

    // layer 2
    k_sdots2<<<6250, 256>>>();
    k_edge2<<<6250, 256>>>();
    k_tgemm<128><<<dim3(GB, 1), 256>>>(2, x);    // pm2
    k_tgemm<128><<<dim3(GB, 2), 256>>>(3, x);    // Y1 & Y2

    k_final<<<(NN*32 + 255)/256, 256>>>(out);
}

// round 5
// speedup vs baseline: 1.2638x; 1.0531x over previous
#include <cuda_runtime.h>
#include <cuda_bf16.h>
#include <math.h>

#define NN 50000
#define NFEAT 128
#define RDIM 128
#define NREL 500
#define NE 800000
#define NEN 100000
#define NET 900000
#define DOUT 128
#define ALPHA 0.2f

// output section offsets (floats)
#define OFF1 (NN*DOUT)            /* out_rel */
#define OFF2 (OFF1 + NREL*DOUT)   /* elu(h_num2) */
#define OFF3 (OFF2 + NN*DOUT)     /* elu(h_unif2) */

// ---------------- scratch (device globals; no allocation allowed) ----------------
static __device__ int  g_cnt[NN];          // zero-init at load; re-zeroed by k_scan each run
static __device__ int  g_rp[NN+1];
static __device__ int  g_cur[NN];
static __device__ int4 g_meta[NET];                       // (e1, idx, ta, tb)
static __device__ __align__(16) float2 g_ss1[NN];
static __device__ __align__(16) float2 g_sd1[NN];
static __device__ __align__(16) float g_cat1[(size_t)NN*512];   // [n][h][wx(128) we(128)]
static __device__ __align__(16) float g_x2[(size_t)NN*128];
static __device__ float g_s2s[NN], g_s2d[NN];
static __device__ __align__(16) float g_acc2[(size_t)NN*512];   // [n][wx wo sx/c so/c]
static __device__ float g_rs2[NN];
static __device__ __align__(16) float g_vvec[6][128];     // [h*3+w], w: 0=src 1=dst 2=rel
static __device__ __align__(8)  float g_srel1[2*NREL];    // [t*2+h]
static __device__ __align__(16) float g_w2[3][128];
static __device__ float g_s2rel[NREL];
static __device__ __align__(16) float g_outrel[NREL*128];
// bf16 hi/lo weights in ORIGINAL [o][k] layout (k contiguous)
static __device__ __align__(16) __nv_bfloat16 g_Bh1[2*64*384];
static __device__ __align__(16) __nv_bfloat16 g_Bl1[2*64*384];
static __device__ __align__(16) __nv_bfloat16 g_Bh2[128*384];
static __device__ __align__(16) __nv_bfloat16 g_Bl2[128*384];

// ---------------- helpers ----------------
__device__ __forceinline__ float lrelu(float z){ return z > 0.f ? z : ALPHA*z; }
__device__ __forceinline__ float eluf(float z){ return z > 0.f ? z : (__expf(z) - 1.f); }
__device__ __forceinline__ float d4(float4 a, float4 b){
    return a.x*b.x + a.y*b.y + a.z*b.z + a.w*b.w;
}
__device__ __forceinline__ float wredsum(float v){
    #pragma unroll
    for (int o = 16; o; o >>= 1) v += __shfl_xor_sync(0xFFFFFFFFu, v, o);
    return v;
}
__device__ __forceinline__ unsigned smem_u32(const void* p){
    return (unsigned)__cvta_generic_to_shared(p);
}
__device__ __forceinline__ void ldsm4(unsigned &r0, unsigned &r1, unsigned &r2, unsigned &r3, unsigned a){
    asm volatile("ldmatrix.sync.aligned.m8n8.x4.shared.b16 {%0,%1,%2,%3},[%4];"
        : "=r"(r0),"=r"(r1),"=r"(r2),"=r"(r3) : "r"(a));
}
__device__ __forceinline__ void mmabf(float* d, const unsigned* a, const unsigned* b){
    asm volatile("mma.sync.aligned.m16n8k16.row.col.f32.bf16.bf16.f32 "
        "{%0,%1,%2,%3},{%4,%5,%6,%7},{%8,%9},{%0,%1,%2,%3};"
        : "+f"(d[0]),"+f"(d[1]),"+f"(d[2]),"+f"(d[3])
        : "r"(a[0]),"r"(a[1]),"r"(a[2]),"r"(a[3]),"r"(b[0]),"r"(b[1]));
}

// ---------------- sort: histogram / scan / scatter ----------------
__global__ void k_hist(const int* __restrict__ el, const int* __restrict__ eln){
    int i = blockIdx.x*256 + threadIdx.x;
    if (i >= NET) return;
    int n = (i < NE) ? __ldcs(el + i) : __ldcs(eln + i - NE);
    atomicAdd(&g_cnt[n], 1);
}

__global__ void k_scan(){
    __shared__ int sp[512];
    int t = threadIdx.x;
    const int C = (NN + 511) / 512;
    int base = t * C;
    int s = 0;
    for (int i = 0; i < C; i++){ int idx = base + i; if (idx < NN) s += g_cnt[idx]; }
    sp[t] = s; __syncthreads();
    for (int off = 1; off < 512; off <<= 1){
        int v = (t >= off) ? sp[t - off] : 0;
        __syncthreads();
        sp[t] += v;
        __syncthreads();
    }
    int pre = (t == 0) ? 0 : sp[t-1];
    for (int i = 0; i < C; i++){
        int idx = base + i;
        if (idx < NN){
            int c = g_cnt[idx];
            g_rp[idx] = pre; g_cur[idx] = pre; pre += c;
            g_cnt[idx] = 0;                    // self-clean for next run
        }
    }
    if (t == 511) g_rp[NN] = NET;
}

__global__ void k_scatter(const int* __restrict__ el, const int* __restrict__ et,
                          const int* __restrict__ eln, const int* __restrict__ etn){
    int i = blockIdx.x*256 + threadIdx.x;
    if (i >= NET) return;
    int n, e1, ta, tb;
    if (i < NE){
        n = __ldcs(el + i); e1 = __ldcs(el + NE + i); ta = __ldcs(et + i); tb = -1;
    } else {
        int j = i - NE;
        n = __ldcs(eln + j); e1 = __ldcs(eln + NEN + j);
        ta = __ldcs(etn + 2*j); tb = __ldcs(etn + 2*j + 1);
    }
    int pos = atomicAdd(&g_cur[n], 1);
    g_meta[pos] = make_int4(e1, i, ta, tb);
}

// ---------------- small precompute ----------------
__global__ void k_prep(const float* __restrict__ ah, const float* __restrict__ a2h,
                       const float* __restrict__ ao, const float* __restrict__ a2o){
    int id = blockIdx.x*256 + threadIdx.x;
    if (id < 49152){
        float v = ah[id];
        __nv_bfloat16 h = __float2bfloat16(v);
        g_Bh1[id] = h;
        g_Bl1[id] = __float2bfloat16(v - __bfloat162float(h));
    } else if (id < 98304){
        int j = id - 49152;
        float v = ao[j];
        __nv_bfloat16 h = __float2bfloat16(v);
        g_Bh2[j] = h;
        g_Bl2[j] = __float2bfloat16(v - __bfloat162float(h));
    } else if (id < 99072){
        int j = id - 98304;
        int m = j / 128, k = j % 128;
        int h = m / 3, w = m % 3;
        float s = 0.f;
        #pragma unroll 4
        for (int o = 0; o < 64; o++)
            s += a2h[h*64 + o] * ah[h*24576 + o*384 + w*128 + k];
        g_vvec[m][k] = s;
    } else if (id < 99456){
        int j = id - 99072;
        int m = j / 128, k = j % 128;
        float s = 0.f;
        #pragma unroll 4
        for (int o = 0; o < 128; o++)
            s += a2o[o] * ao[o*384 + m*128 + k];
        g_w2[m][k] = s;
    }
}

__global__ void k_outrel(const float* __restrict__ rel, const float* __restrict__ W,
                         float* __restrict__ out){
    int id = blockIdx.x*256 + threadIdx.x;
    if (id >= NREL*128) return;
    int t = id / 128, o = id % 128;
    float s = 0.f;
    #pragma unroll 4
    for (int k = 0; k < 128; k++) s += rel[t*128 + k] * W[k*128 + o];
    g_outrel[id] = s;
    out[OFF1 + id] = s;
}

__global__ void k_srel(const float* __restrict__ rel){
    int id = blockIdx.x*256 + threadIdx.x;
    if (id < 1000){
        int t = id >> 1, h = id & 1;
        const float* v = g_vvec[h*3 + 2];
        float s = 0.f;
        #pragma unroll 4
        for (int k = 0; k < 128; k++) s += rel[t*128 + k] * v[k];
        g_srel1[id] = s;
    } else if (id < 1500){
        int t = id - 1000;
        float s = 0.f;
        #pragma unroll 4
        for (int k = 0; k < 128; k++) s += g_outrel[t*128 + k] * g_w2[2][k];
        g_s2rel[t] = s;
    }
}

// ---------------- per-node scalar dots (also warm L2 with x / x2) ----------------
__global__ void k_sdots1(const float* __restrict__ x){
    int w = (blockIdx.x*blockDim.x + threadIdx.x) >> 5;
    int l = threadIdx.x & 31;
    if (w >= NN) return;
    float4 xv = ((const float4*)x)[w*32 + l];
    float p0 = d4(xv, ((const float4*)g_vvec[0])[l]);
    float p1 = d4(xv, ((const float4*)g_vvec[3])[l]);
    float p2 = d4(xv, ((const float4*)g_vvec[1])[l]);
    float p3 = d4(xv, ((const float4*)g_vvec[4])[l]);
    p0 = wredsum(p0); p1 = wredsum(p1); p2 = wredsum(p2); p3 = wredsum(p3);
    if (l == 0){
        g_ss1[w] = make_float2(p0, p1);
        g_sd1[w] = make_float2(p2, p3);
    }
}

__global__ void k_sdots2(){
    int w = (blockIdx.x*blockDim.x + threadIdx.x) >> 5;
    int l = threadIdx.x & 31;
    if (w >= NN) return;
    float4 xv = ((const float4*)g_x2)[w*32 + l];
    float p0 = d4(xv, ((const float4*)g_w2[0])[l]);
    float p1 = d4(xv, ((const float4*)g_w2[1])[l]);
    p0 = wredsum(p0); p1 = wredsum(p1);
    if (l == 0){ g_s2s[w] = p0; g_s2d[w] = p1; }
}

// ---------------- layer 1 edge pass (CSR, warp per node) ----------------
__global__ void k_edge1(const float* __restrict__ x, const float* __restrict__ eemb,
                        const float* __restrict__ rel){
    int w = (blockIdx.x*blockDim.x + threadIdx.x) >> 5;
    int l = threadIdx.x & 31;
    if (w >= NN) return;
    int beg = g_rp[w], end = g_rp[w+1];

    const float4* x4 = (const float4*)x;
    const float4* e4 = (const float4*)eemb;
    const float4* r4 = (const float4*)rel;
    float4 vr0 = ((const float4*)g_vvec[2])[l];
    float4 vr1 = ((const float4*)g_vvec[5])[l];
    float2 ssn = g_ss1[w];

    float4 wx0 = {0,0,0,0}, wx1 = {0,0,0,0}, we0 = {0,0,0,0}, we1 = {0,0,0,0};
    float rs0 = 0.f, rs1 = 0.f;

    int4 mt;
    if (beg < end) mt = __ldcs(&g_meta[beg]);
    for (int p = beg; p < end; p++){
        int4 cur = mt;
        if (p + 1 < end) mt = __ldcs(&g_meta[p+1]);   // prefetch next meta
        int e1 = cur.x, idx = cur.y;
        float4 xv = x4[(size_t)e1*32 + l];
        float4 ev;
        float sr0, sr1;
        if (idx < NE){
            ev = __ldcs(&e4[(size_t)idx*32 + l]);     // streaming: don't pollute L2
            float q0 = d4(ev, vr0);
            float q1 = d4(ev, vr1);
            #pragma unroll
            for (int o = 16; o; o >>= 1){
                q0 += __shfl_xor_sync(0xFFFFFFFFu, q0, o);
                q1 += __shfl_xor_sync(0xFFFFFFFFu, q1, o);
            }
            sr0 = q0; sr1 = q1;
        } else {
            int ta = cur.z, tb = cur.w;
            float4 ra = r4[ta*32 + l];
            float4 rb = r4[tb*32 + l];
            ev = make_float4(ra.x+rb.x, ra.y+rb.y, ra.z+rb.z, ra.w+rb.w);
            float2 sa = *(const float2*)(g_srel1 + ta*2);
            float2 sb = *(const float2*)(g_srel1 + tb*2);
            sr0 = sa.x + sb.x; sr1 = sa.y + sb.y;
        }
        float2 sd = g_sd1[e1];
        float z0 = ssn.x + sd.x + sr0;
        float z1 = ssn.y + sd.y + sr1;
        float ee0 = __expf(-lrelu(z0));
        float ee1 = __expf(-lrelu(z1));
        rs0 += ee0; rs1 += ee1;
        wx0.x += ee0*xv.x; wx0.y += ee0*xv.y; wx0.z += ee0*xv.z; wx0.w += ee0*xv.w;
        wx1.x += ee1*xv.x; wx1.y += ee1*xv.y; wx1.z += ee1*xv.z; wx1.w += ee1*xv.w;
        we0.x += ee0*ev.x; we0.y += ee0*ev.y; we0.z += ee0*ev.z; we0.w += ee0*ev.w;
        we1.x += ee1*ev.x; we1.y += ee1*ev.y; we1.z += ee1*ev.z; we1.w += ee1*ev.w;
    }
    float i0 = (end > beg) ? (1.f / rs0) : 0.f;
    float i1 = (end > beg) ? (1.f / rs1) : 0.f;
    float4* c4 = (float4*)g_cat1;
    size_t b = (size_t)w*128;
    __stcs(&c4[b +  0 + l], make_float4(wx0.x*i0, wx0.y*i0, wx0.z*i0, wx0.w*i0));
    __stcs(&c4[b + 32 + l], make_float4(we0.x*i0, we0.y*i0, we0.z*i0, we0.w*i0));
    __stcs(&c4[b + 64 + l], make_float4(wx1.x*i1, wx1.y*i1, wx1.z*i1, wx1.w*i1));
    __stcs(&c4[b + 96 + l], make_float4(we1.x*i1, we1.y*i1, we1.z*i1, we1.w*i1));
}

// ---------------- layer 2 edge pass ----------------
__global__ void k_edge2(){
    int w = (blockIdx.x*blockDim.x + threadIdx.x) >> 5;
    int l = threadIdx.x & 31;
    if (w >= NN) return;
    int beg = g_rp[w], end = g_rp[w+1];

    const float4* x4 = (const float4*)g_x2;
    const float4* o4 = (const float4*)g_outrel;
    float ssn = g_s2s[w];

    float4 wx = {0,0,0,0}, wo = {0,0,0,0}, sx = {0,0,0,0}, so = {0,0,0,0};
    float rs = 0.f;

    int4 mt;
    if (beg < end) mt = __ldcs(&g_meta[beg]);
    for (int p = beg; p < end; p++){
        int4 cur = mt;
        if (p + 1 < end) mt = __ldcs(&g_meta[p+1]);
        int e1 = cur.x, ta = cur.z, tb = cur.w;
        float4 xv = x4[(size_t)e1*32 + l];
        float4 ov;
        float sr;
        if (tb < 0){
            ov = o4[ta*32 + l];
            sr = g_s2rel[ta];
        } else {
            float4 ra = o4[ta*32 + l];
            float4 rb = o4[tb*32 + l];
            ov = make_float4(ra.x+rb.x, ra.y+rb.y, ra.z+rb.z, ra.w+rb.w);
            sr = g_s2rel[ta] + g_s2rel[tb];
        }
        float z = ssn + g_s2d[e1] + sr;
        float ee = __expf(-lrelu(z));
        rs += ee;
        wx.x += ee*xv.x; wx.y += ee*xv.y; wx.z += ee*xv.z; wx.w += ee*xv.w;
        wo.x += ee*ov.x; wo.y += ee*ov.y; wo.z += ee*ov.z; wo.w += ee*ov.w;
        sx.x += xv.x; sx.y += xv.y; sx.z += xv.z; sx.w += xv.w;
        so.x += ov.x; so.y += ov.y; so.z += ov.z; so.w += ov.w;
    }
    int cnt = end - beg;
    float ic = cnt ? (1.f / (float)cnt) : 0.f;
    float4* a4 = (float4*)g_acc2;
    size_t b = (size_t)w*128;
    __stcs(&a4[b +  0 + l], wx);
    __stcs(&a4[b + 32 + l], wo);
    __stcs(&a4[b + 64 + l], make_float4(sx.x*ic, sx.y*ic, sx.z*ic, sx.w*ic));
    __stcs(&a4[b + 96 + l], make_float4(so.x*ic, so.y*ic, so.z*ic, so.w*ic));
    if (l == 0) g_rs2[w] = rs;
}

// ---------------- layer-1 GEMM: x2 = elu([x | cat1_h] @ a_heads_h^T), BN=64 ----------------
__global__ __launch_bounds__(256) void k_tgemm1(const float* __restrict__ Aext){
    const int h = blockIdx.y;
    const float* A1 = Aext;                    // x, lda 128
    const float* A2 = g_cat1 + h*256;          // lda 512
    const __nv_bfloat16* Bh = g_Bh1 + h*24576;
    const __nv_bfloat16* Bl = g_Bl1 + h*24576;
    const int K1 = 128, K = 384, M = NN;
    constexpr int BN = 64, NF = BN/16;

    __shared__ __align__(16) __nv_bfloat16 Ah[128][40];
    __shared__ __align__(16) __nv_bfloat16 Al[128][40];
    __shared__ __align__(16) __nv_bfloat16 Bhs[BN][40];
    __shared__ __align__(16) __nv_bfloat16 Bls[BN][40];

    int tid = threadIdx.x, lane = tid & 31, warp = tid >> 5;
    int wm = (warp & 3) * 32;
    int wn = (warp >> 2) * (BN/2);
    int bm0 = blockIdx.x * 128;

    float d[2][NF][4];
    #pragma unroll
    for (int f = 0; f < 2; f++)
        #pragma unroll
        for (int j = 0; j < NF; j++)
            #pragma unroll
            for (int q = 0; q < 4; q++) d[f][j][q] = 0.f;

    int ar = tid >> 1, akq = (tid & 1) * 16;
    int bn = tid / 4, bkq = (tid % 4) * 8;
    int m = bm0 + ar;
    bool mv = m < M;

    for (int k0 = 0; k0 < K; k0 += 32){
        const float* asrc;
        bool strm;
        if (k0 < K1){ asrc = A1 + (size_t)m*128 + k0 + akq; strm = false; }
        else        { asrc = A2 + (size_t)m*512 + (k0-K1) + akq; strm = true; }
        #pragma unroll
        for (int j = 0; j < 16; j += 4){
            float4 v = make_float4(0,0,0,0);
            if (mv) v = strm ? __ldcs((const float4*)(asrc + j))
                             : *(const float4*)(asrc + j);
            __nv_bfloat162 h0 = __floats2bfloat162_rn(v.x, v.y);
            __nv_bfloat162 h1 = __floats2bfloat162_rn(v.z, v.w);
            __nv_bfloat162 l0 = __floats2bfloat162_rn(v.x - __low2float(h0),
                                                      v.y - __high2float(h0));
            __nv_bfloat162 l1 = __floats2bfloat162_rn(v.z - __low2float(h1),
                                                      v.w - __high2float(h1));
            *(__nv_bfloat162*)&Ah[ar][akq+j]   = h0;
            *(__nv_bfloat162*)&Ah[ar][akq+j+2] = h1;
            *(__nv_bfloat162*)&Al[ar][akq+j]   = l0;
            *(__nv_bfloat162*)&Al[ar][akq+j+2] = l1;
        }
        *(uint4*)&Bhs[bn][bkq] = *(const uint4*)(Bh + (size_t)bn*384 + k0 + bkq);
        *(uint4*)&Bls[bn][bkq] = *(const uint4*)(Bl + (size_t)bn*384 + k0 + bkq);
        __syncthreads();

        #pragma unroll
        for (int kk = 0; kk < 32; kk += 16){
            unsigned ah_[2][4], al_[2][4], bh_[NF][2], bl_[NF][2];
            #pragma unroll
            for (int f = 0; f < 2; f++){
                int rrow = wm + f*16 + (lane & 15);
                int rcol = kk + (lane >> 4) * 8;
                ldsm4(ah_[f][0], ah_[f][1], ah_[f][2], ah_[f][3], smem_u32(&Ah[rrow][rcol]));
                ldsm4(al_[f][0], al_[f][1], al_[f][2], al_[f][3], smem_u32(&Al[rrow][rcol]));
            }
            #pragma unroll
            for (int g = 0; g < NF/2; g++){
                int nb = wn + g*16 + ((lane >> 4) << 3) + (lane & 7);
                int kc = kk + ((lane >> 3) & 1) * 8;
                ldsm4(bh_[2*g][0], bh_[2*g][1], bh_[2*g+1][0], bh_[2*g+1][1], smem_u32(&Bhs[nb][kc]));
                ldsm4(bl_[2*g][0], bl_[2*g][1], bl_[2*g+1][0], bl_[2*g+1][1], smem_u32(&Bls[nb][kc]));
            }
            #pragma unroll
            for (int f = 0; f < 2; f++)
                #pragma unroll
                for (int j = 0; j < NF; j++){
                    mmabf(d[f][j], ah_[f], bh_[j]);
                    mmabf(d[f][j], ah_[f], bl_[j]);
                    mmabf(d[f][j], al_[f], bh_[j]);
                }
        }
        __syncthreads();
    }

    int gid = lane >> 2, tig = lane & 3;
    #pragma unroll
    for (int f = 0; f < 2; f++){
        #pragma unroll
        for (int j = 0; j < NF; j++){
            int col = h*64 + wn + j*8 + tig*2;
            int m0r = bm0 + wm + f*16 + gid;
            #pragma unroll
            for (int half = 0; half < 2; half++){
                int mm = m0r + half*8;
                if (mm >= M) continue;
                bool live = (g_rp[mm+1] - g_rp[mm]) > 0;
                float v0 = live ? eluf(d[f][j][half*2+0]) : 0.f;
                float v1 = live ? eluf(d[f][j][half*2+1]) : 0.f;
                *(float2*)&g_x2[(size_t)mm*128 + col] = make_float2(v0, v1);
            }
        }
    }
}

// ---------------- layer-2 fused GEMM: hn/un with direct output epilogue ----------------
// blockIdx.y: 0 -> hn = [rs*x2 | wx,wo] @ B ; writes out[0:..] (elu(hn/rs)) and out[OFF2..] (elu(hn))
//             1 -> un = [x2 | sx/c,so/c] @ B ; writes out[OFF3..] (elu(un))
__global__ __launch_bounds__(256) void k_tgemm2(float* __restrict__ out){
    const int which = blockIdx.y;
    const float* A2 = g_acc2 + (which ? 256 : 0);
    const int K1 = 128, K = 384, M = NN;
    constexpr int BN = 128, NF = BN/16;

    __shared__ __align__(16) __nv_bfloat16 Ah[128][40];
    __shared__ __align__(16) __nv_bfloat16 Al[128][40];
    __shared__ __align__(16) __nv_bfloat16 Bhs[BN][40];
    __shared__ __align__(16) __nv_bfloat16 Bls[BN][40];

    int tid = threadIdx.x, lane = tid & 31, warp = tid >> 5;
    int wm = (warp & 3) * 32;
    int wn = (warp >> 2) * 64;
    int bm0 = blockIdx.x * 128;

    float d[2][NF][4];
    #pragma unroll
    for (int f = 0; f < 2; f++)
        #pragma unroll
        for (int j = 0; j < NF; j++)
            #pragma unroll
            for (int q = 0; q < 4; q++) d[f][j][q] = 0.f;

    int ar = tid >> 1, akq = (tid & 1) * 16;
    int bn = tid / 2, bkq = (tid & 1) * 16;
    int m = bm0 + ar;
    bool mv = m < M;
    float scl = 1.f;
    if (which == 0 && mv) scl = g_rs2[m];   // hn: rs-scaled x2 rows

    for (int k0 = 0; k0 < K; k0 += 32){
        const float* asrc;
        bool strm; float s;
        if (k0 < K1){ asrc = g_x2 + (size_t)m*128 + k0 + akq; strm = false; s = scl; }
        else        { asrc = A2 + (size_t)m*512 + (k0-K1) + akq; strm = true; s = 1.f; }
        #pragma unroll
        for (int j = 0; j < 16; j += 4){
            float4 v = make_float4(0,0,0,0);
            if (mv) v = strm ? __ldcs((const float4*)(asrc + j))
                             : *(const float4*)(asrc + j);
            v.x *= s; v.y *= s; v.z *= s; v.w *= s;
            __nv_bfloat162 h0 = __floats2bfloat162_rn(v.x, v.y);
            __nv_bfloat162 h1 = __floats2bfloat162_rn(v.z, v.w);
            __nv_bfloat162 l0 = __floats2bfloat162_rn(v.x - __low2float(h0),
                                                      v.y - __high2float(h0));
            __nv_bfloat162 l1 = __floats2bfloat162_rn(v.z - __low2float(h1),
                                                      v.w - __high2float(h1));
            *(__nv_bfloat162*)&Ah[ar][akq+j]   = h0;
            *(__nv_bfloat162*)&Ah[ar][akq+j+2] = h1;
            *(__nv_bfloat162*)&Al[ar][akq+j]   = l0;
            *(__nv_bfloat162*)&Al[ar][akq+j+2] = l1;
        }
        #pragma unroll
        for (int j = 0; j < 16; j += 8){
            *(uint4*)&Bhs[bn][bkq+j] = *(const uint4*)(g_Bh2 + (size_t)bn*384 + k0 + bkq + j);
            *(uint4*)&Bls[bn][bkq+j] = *(const uint4*)(g_Bl2 + (size_t)bn*384 + k0 + bkq + j);
        }
        __syncthreads();

        #pragma unroll
        for (int kk = 0; kk < 32; kk += 16){
            unsigned ah_[2][4], al_[2][4], bh_[NF][2], bl_[NF][2];
            #pragma unroll
            for (int f = 0; f < 2; f++){
                int rrow = wm + f*16 + (lane & 15);
                int rcol = kk + (lane >> 4) * 8;
                ldsm4(ah_[f][0], ah_[f][1], ah_[f][2], ah_[f][3], smem_u32(&Ah[rrow][rcol]));
                ldsm4(al_[f][0], al_[f][1], al_[f][2], al_[f][3], smem_u32(&Al[rrow][rcol]));
            }
            #pragma unroll
            for (int g = 0; g < NF/2; g++){
                int nb = wn + g*16 + ((lane >> 4) << 3) + (lane & 7);
                int kc = kk + ((lane >> 3) & 1) * 8;
                ldsm4(bh_[2*g][0], bh_[2*g][1], bh_[2*g+1][0], bh_[2*g+1][1], smem_u32(&Bhs[nb][kc]));
                ldsm4(bl_[2*g][0], bl_[2*g][1], bl_[2*g+1][0], bl_[2*g+1][1], smem_u32(&Bls[nb][kc]));
            }
            #pragma unroll
            for (int f = 0; f < 2; f++)
                #pragma unroll
                for (int j = 0; j < NF; j++){
                    mmabf(d[f][j], ah_[f], bh_[j]);
                    mmabf(d[f][j], ah_[f], bl_[j]);
                    mmabf(d[f][j], al_[f], bh_[j]);
                }
        }
        __syncthreads();
    }

    // fused epilogue -> d_out
    int gid = lane >> 2, tig = lane & 3;
    #pragma unroll
    for (int f = 0; f < 2; f++){
        #pragma unroll
        for (int half = 0; half < 2; half++){
            int mm = bm0 + wm + f*16 + gid + half*8;
            if (mm >= M) continue;
            float inv = 0.f;
            if (which == 0){
                float rs = g_rs2[mm];
                inv = (rs > 0.f) ? (1.f / rs) : 0.f;
            }
            #pragma unroll
            for (int j = 0; j < NF; j++){
                int col = wn + j*8 + tig*2;
                float v0 = d[f][j][half*2+0];
                float v1 = d[f][j][half*2+1];
                size_t o = (size_t)mm*128 + col;
                if (which == 0){
                    __stcs((float2*)&out[o],        make_float2(eluf(v0*inv), eluf(v1*inv)));
                    __stcs((float2*)&out[OFF2 + o], make_float2(eluf(v0),     eluf(v1)));
                } else {
                    __stcs((float2*)&out[OFF3 + o], make_float2(eluf(v0), eluf(v1)));
                }
            }
        }
    }
}

// ---------------- launcher ----------------
extern "C" void kernel_launch(void* const* d_in, const int* in_sizes, int n_in,
                              void* d_out, int out_size){
    const float* x    = (const float*)d_in[0];
    const float* rel  = (const float*)d_in[1];
    const float* eemb = (const float*)d_in[2];
    const float* ah   = (const float*)d_in[3];
    const float* a2h  = (const float*)d_in[4];
    const float* W    = (const float*)d_in[5];
    const float* ao   = (const float*)d_in[6];
    const float* a2o  = (const float*)d_in[7];
    const int* el  = (const int*)d_in[8];
    const int* et  = (const int*)d_in[9];
    const int* eln = (const int*)d_in[10];
    const int* etn = (const int*)d_in[11];
    float* out = (float*)d_out;

    const int GB = (NN + 127) / 128;   // 391

    // CSR build (g_cnt arrives zeroed: zero-init + self-clean in k_scan)
    k_hist<<<(NET + 255)/256, 256>>>(el, eln);
    k_scan<<<1, 512>>>();
    k_scatter<<<(NET + 255)/256, 256>>>(el, et, eln, etn);

    // small precompute
    k_prep<<<(99456 + 255)/256, 256>>>(ah, a2h, ao, a2o);
    k_outrel<<<(NREL*128 + 255)/256, 256>>>(rel, W, out);
    k_srel<<<(1500 + 255)/256, 256>>>(rel);

    // layer 1
    k_sdots1<<<6250, 256>>>(x);
    k_edge1<<<6250, 256>>>(x, eemb, rel);
    k_tgemm1<<<dim3(GB, 2), 256>>>(x);

    // layer 2
    k_sdots2<<<6250, 256>>>();
    k_edge2<<<6250, 256>>>();
    k_tgemm2<<<dim3(GB, 2), 256>>>(out);
}

// round 6
// speedup vs baseline: 1.3755x; 1.0884x over previous
#include <cuda_runtime.h>
#include <cuda_bf16.h>
#include <math.h>

#define NN 50000
#define NFEAT 128
#define RDIM 128
#define NREL 500
#define NE 800000
#define NEN 100000
#define NET 900000
#define DOUT 128
#define ALPHA 0.2f

// output section offsets (floats)
#define OFF1 (NN*DOUT)            /* out_rel */
#define OFF2 (OFF1 + NREL*DOUT)   /* elu(h_num2) */
#define OFF3 (OFF2 + NN*DOUT)     /* elu(h_unif2) */

// ---------------- scratch (device globals; no allocation allowed) ----------------
static __device__ int  g_cnt[NN];          // zero-init at load; re-zeroed by k_scan each run
static __device__ int  g_rp[NN+1];
static __device__ int  g_cur[NN];
static __device__ int4 g_meta[NET];                       // (e1, idx, ta, tb)
static __device__ __align__(16) float2 g_ss1[NN];
static __device__ __align__(16) float2 g_sd1[NN];
static __device__ __align__(16) float g_cat1[(size_t)NN*512];   // [n][h][wx(128) we(128)]
static __device__ __align__(16) float g_x2[(size_t)NN*128];
static __device__ float g_s2s[NN], g_s2d[NN];
static __device__ __align__(16) float g_acc2[(size_t)NN*512];   // [n][wx wo sx/c so/c]
static __device__ float g_rs2[NN];
static __device__ __align__(16) float g_vvec[6][128];     // [h*3+w], w: 0=src 1=dst 2=rel
static __device__ __align__(8)  float g_srel1[2*NREL];    // [t*2+h]
static __device__ __align__(16) float g_w2[3][128];
static __device__ float g_s2rel[NREL];
static __device__ __align__(16) float g_outrel[NREL*128];
// bf16 hi/lo weights in ORIGINAL [o][k] layout (k contiguous)
static __device__ __align__(16) __nv_bfloat16 g_Bh1[2*64*384];
static __device__ __align__(16) __nv_bfloat16 g_Bl1[2*64*384];
static __device__ __align__(16) __nv_bfloat16 g_Bh2[128*384];
static __device__ __align__(16) __nv_bfloat16 g_Bl2[128*384];

// ---------------- helpers ----------------
__device__ __forceinline__ float lrelu(float z){ return z > 0.f ? z : ALPHA*z; }
__device__ __forceinline__ float eluf(float z){ return z > 0.f ? z : (__expf(z) - 1.f); }
__device__ __forceinline__ float d4(float4 a, float4 b){
    return a.x*b.x + a.y*b.y + a.z*b.z + a.w*b.w;
}
__device__ __forceinline__ float wredsum(float v){
    #pragma unroll
    for (int o = 16; o; o >>= 1) v += __shfl_xor_sync(0xFFFFFFFFu, v, o);
    return v;
}
__device__ __forceinline__ void fma4(float4 &acc, float s, float4 v){
    acc.x += s*v.x; acc.y += s*v.y; acc.z += s*v.z; acc.w += s*v.w;
}
__device__ __forceinline__ unsigned smem_u32(const void* p){
    return (unsigned)__cvta_generic_to_shared(p);
}
__device__ __forceinline__ void ldsm4(unsigned &r0, unsigned &r1, unsigned &r2, unsigned &r3, unsigned a){
    asm volatile("ldmatrix.sync.aligned.m8n8.x4.shared.b16 {%0,%1,%2,%3},[%4];"
        : "=r"(r0),"=r"(r1),"=r"(r2),"=r"(r3) : "r"(a));
}
__device__ __forceinline__ void mmabf(float* d, const unsigned* a, const unsigned* b){
    asm volatile("mma.sync.aligned.m16n8k16.row.col.f32.bf16.bf16.f32 "
        "{%0,%1,%2,%3},{%4,%5,%6,%7},{%8,%9},{%0,%1,%2,%3};"
        : "+f"(d[0]),"+f"(d[1]),"+f"(d[2]),"+f"(d[3])
        : "r"(a[0]),"r"(a[1]),"r"(a[2]),"r"(a[3]),"r"(b[0]),"r"(b[1]));
}

// ---------------- sort: histogram / scan / scatter ----------------
__global__ void k_hist(const int* __restrict__ el, const int* __restrict__ eln){
    int i = blockIdx.x*256 + threadIdx.x;
    if (i >= NET) return;
    int n = (i < NE) ? __ldcs(el + i) : __ldcs(eln + i - NE);
    atomicAdd(&g_cnt[n], 1);
}

__global__ void k_scan(){
    __shared__ int sp[1024];
    int t = threadIdx.x;
    const int C = (NN + 1023) / 1024;   // 49
    int base = t * C;
    int s = 0;
    #pragma unroll 7
    for (int i = 0; i < C; i++){ int idx = base + i; if (idx < NN) s += g_cnt[idx]; }
    sp[t] = s; __syncthreads();
    for (int off = 1; off < 1024; off <<= 1){
        int v = (t >= off) ? sp[t - off] : 0;
        __syncthreads();
        sp[t] += v;
        __syncthreads();
    }
    int pre = (t == 0) ? 0 : sp[t-1];
    for (int i = 0; i < C; i++){
        int idx = base + i;
        if (idx < NN){
            int c = g_cnt[idx];
            g_rp[idx] = pre; g_cur[idx] = pre; pre += c;
            g_cnt[idx] = 0;                    // self-clean for next run
        }
    }
    if (t == 1023) g_rp[NN] = NET;
}

__global__ void k_scatter(const int* __restrict__ el, const int* __restrict__ et,
                          const int* __restrict__ eln, const int* __restrict__ etn){
    int i = blockIdx.x*256 + threadIdx.x;
    if (i >= NET) return;
    int n, e1, ta, tb;
    if (i < NE){
        n = __ldcs(el + i); e1 = __ldcs(el + NE + i); ta = __ldcs(et + i); tb = -1;
    } else {
        int j = i - NE;
        n = __ldcs(eln + j); e1 = __ldcs(eln + NEN + j);
        ta = __ldcs(etn + 2*j); tb = __ldcs(etn + 2*j + 1);
    }
    int pos = atomicAdd(&g_cur[n], 1);
    g_meta[pos] = make_int4(e1, i, ta, tb);
}

// ---------------- small precompute ----------------
__global__ void k_prep(const float* __restrict__ ah, const float* __restrict__ a2h,
                       const float* __restrict__ ao, const float* __restrict__ a2o){
    int id = blockIdx.x*256 + threadIdx.x;
    if (id < 49152){
        float v = ah[id];
        __nv_bfloat16 h = __float2bfloat16(v);
        g_Bh1[id] = h;
        g_Bl1[id] = __float2bfloat16(v - __bfloat162float(h));
    } else if (id < 98304){
        int j = id - 49152;
        float v = ao[j];
        __nv_bfloat16 h = __float2bfloat16(v);
        g_Bh2[j] = h;
        g_Bl2[j] = __float2bfloat16(v - __bfloat162float(h));
    } else if (id < 99072){
        int j = id - 98304;
        int m = j / 128, k = j % 128;
        int h = m / 3, w = m % 3;
        float s = 0.f;
        #pragma unroll 4
        for (int o = 0; o < 64; o++)
            s += a2h[h*64 + o] * ah[h*24576 + o*384 + w*128 + k];
        g_vvec[m][k] = s;
    } else if (id < 99456){
        int j = id - 99072;
        int m = j / 128, k = j % 128;
        float s = 0.f;
        #pragma unroll 4
        for (int o = 0; o < 128; o++)
            s += a2o[o] * ao[o*384 + m*128 + k];
        g_w2[m][k] = s;
    }
}

__global__ void k_outrel(const float* __restrict__ rel, const float* __restrict__ W,
                         float* __restrict__ out){
    int id = blockIdx.x*256 + threadIdx.x;
    if (id >= NREL*128) return;
    int t = id / 128, o = id % 128;
    float s = 0.f;
    #pragma unroll 4
    for (int k = 0; k < 128; k++) s += rel[t*128 + k] * W[k*128 + o];
    g_outrel[id] = s;
    out[OFF1 + id] = s;
}

__global__ void k_srel(const float* __restrict__ rel){
    int id = blockIdx.x*256 + threadIdx.x;
    if (id < 1000){
        int t = id >> 1, h = id & 1;
        const float* v = g_vvec[h*3 + 2];
        float s = 0.f;
        #pragma unroll 4
        for (int k = 0; k < 128; k++) s += rel[t*128 + k] * v[k];
        g_srel1[id] = s;
    } else if (id < 1500){
        int t = id - 1000;
        float s = 0.f;
        #pragma unroll 4
        for (int k = 0; k < 128; k++) s += g_outrel[t*128 + k] * g_w2[2][k];
        g_s2rel[t] = s;
    }
}

// ---------------- per-node scalar dots ----------------
__global__ void k_sdots1(const float* __restrict__ x){
    int w = (blockIdx.x*blockDim.x + threadIdx.x) >> 5;
    int l = threadIdx.x & 31;
    if (w >= NN) return;
    float4 xv = ((const float4*)x)[w*32 + l];
    float p0 = d4(xv, ((const float4*)g_vvec[0])[l]);
    float p1 = d4(xv, ((const float4*)g_vvec[3])[l]);
    float p2 = d4(xv, ((const float4*)g_vvec[1])[l]);
    float p3 = d4(xv, ((const float4*)g_vvec[4])[l]);
    p0 = wredsum(p0); p1 = wredsum(p1); p2 = wredsum(p2); p3 = wredsum(p3);
    if (l == 0){
        g_ss1[w] = make_float2(p0, p1);
        g_sd1[w] = make_float2(p2, p3);
    }
}

__global__ void k_sdots2(){
    int w = (blockIdx.x*blockDim.x + threadIdx.x) >> 5;
    int l = threadIdx.x & 31;
    if (w >= NN) return;
    float4 xv = ((const float4*)g_x2)[w*32 + l];
    float p0 = d4(xv, ((const float4*)g_w2[0])[l]);
    float p1 = d4(xv, ((const float4*)g_w2[1])[l]);
    p0 = wredsum(p0); p1 = wredsum(p1);
    if (l == 0){ g_s2s[w] = p0; g_s2d[w] = p1; }
}

// ---------------- layer 1 edge pass (CSR, warp per node, x2 unroll) ----------------
__global__ void k_edge1(const float* __restrict__ x, const float* __restrict__ eemb,
                        const float* __restrict__ rel){
    int w = (blockIdx.x*blockDim.x + threadIdx.x) >> 5;
    int l = threadIdx.x & 31;
    if (w >= NN) return;
    int beg = g_rp[w], end = g_rp[w+1];

    const float4* x4 = (const float4*)x;
    const float4* e4 = (const float4*)eemb;
    const float4* r4 = (const float4*)rel;
    float4 vr0 = ((const float4*)g_vvec[2])[l];
    float4 vr1 = ((const float4*)g_vvec[5])[l];
    float2 ssn = g_ss1[w];

    float4 wx0 = {0,0,0,0}, wx1 = {0,0,0,0}, we0 = {0,0,0,0}, we1 = {0,0,0,0};
    float rs0 = 0.f, rs1 = 0.f;

    int p = beg;
    // -------- paired iterations: two edges, interleaved reduction chains --------
    for (; p + 1 < end; p += 2){
        int4 ca = __ldcs(&g_meta[p]);
        int4 cb = __ldcs(&g_meta[p+1]);
        // issue all gathers up front (max MLP)
        float4 xva = x4[(size_t)ca.x*32 + l];
        float4 xvb = x4[(size_t)cb.x*32 + l];
        float2 sda = g_sd1[ca.x];
        float2 sdb = g_sd1[cb.x];
        bool dira = ca.y < NE, dirb = cb.y < NE;
        float4 eva, evb;
        float sr0a = 0.f, sr1a = 0.f, sr0b = 0.f, sr1b = 0.f;
        float q0a = 0.f, q1a = 0.f, q0b = 0.f, q1b = 0.f;
        if (dira) eva = __ldcs(&e4[(size_t)ca.y*32 + l]);
        else {
            float4 ra = r4[ca.z*32 + l];
            float4 rb = r4[ca.w*32 + l];
            eva = make_float4(ra.x+rb.x, ra.y+rb.y, ra.z+rb.z, ra.w+rb.w);
            float2 sa = *(const float2*)(g_srel1 + ca.z*2);
            float2 sb = *(const float2*)(g_srel1 + ca.w*2);
            sr0a = sa.x + sb.x; sr1a = sa.y + sb.y;
        }
        if (dirb) evb = __ldcs(&e4[(size_t)cb.y*32 + l]);
        else {
            float4 ra = r4[cb.z*32 + l];
            float4 rb = r4[cb.w*32 + l];
            evb = make_float4(ra.x+rb.x, ra.y+rb.y, ra.z+rb.z, ra.w+rb.w);
            float2 sa = *(const float2*)(g_srel1 + cb.z*2);
            float2 sb = *(const float2*)(g_srel1 + cb.w*2);
            sr0b = sa.x + sb.x; sr1b = sa.y + sb.y;
        }
        if (dira){ q0a = d4(eva, vr0); q1a = d4(eva, vr1); }
        if (dirb){ q0b = d4(evb, vr0); q1b = d4(evb, vr1); }
        // interleaved shfl chains: 4 independent chains pipeline through the SHFL unit
        #pragma unroll
        for (int o = 16; o; o >>= 1){
            q0a += __shfl_xor_sync(0xFFFFFFFFu, q0a, o);
            q1a += __shfl_xor_sync(0xFFFFFFFFu, q1a, o);
            q0b += __shfl_xor_sync(0xFFFFFFFFu, q0b, o);
            q1b += __shfl_xor_sync(0xFFFFFFFFu, q1b, o);
        }
        if (dira){ sr0a = q0a; sr1a = q1a; }
        if (dirb){ sr0b = q0b; sr1b = q1b; }
        float ee0a = __expf(-lrelu(ssn.x + sda.x + sr0a));
        float ee1a = __expf(-lrelu(ssn.y + sda.y + sr1a));
        float ee0b = __expf(-lrelu(ssn.x + sdb.x + sr0b));
        float ee1b = __expf(-lrelu(ssn.y + sdb.y + sr1b));
        rs0 += ee0a + ee0b; rs1 += ee1a + ee1b;
        fma4(wx0, ee0a, xva); fma4(wx0, ee0b, xvb);
        fma4(wx1, ee1a, xva); fma4(wx1, ee1b, xvb);
        fma4(we0, ee0a, eva); fma4(we0, ee0b, evb);
        fma4(we1, ee1a, eva); fma4(we1, ee1b, evb);
    }
    // -------- tail (0 or 1 edge) --------
    if (p < end){
        int4 ca = __ldcs(&g_meta[p]);
        float4 xva = x4[(size_t)ca.x*32 + l];
        float2 sda = g_sd1[ca.x];
        float4 eva;
        float sr0a, sr1a;
        if (ca.y < NE){
            eva = __ldcs(&e4[(size_t)ca.y*32 + l]);
            float q0 = d4(eva, vr0), q1 = d4(eva, vr1);
            #pragma unroll
            for (int o = 16; o; o >>= 1){
                q0 += __shfl_xor_sync(0xFFFFFFFFu, q0, o);
                q1 += __shfl_xor_sync(0xFFFFFFFFu, q1, o);
            }
            sr0a = q0; sr1a = q1;
        } else {
            float4 ra = r4[ca.z*32 + l];
            float4 rb = r4[ca.w*32 + l];
            eva = make_float4(ra.x+rb.x, ra.y+rb.y, ra.z+rb.z, ra.w+rb.w);
            float2 sa = *(const float2*)(g_srel1 + ca.z*2);
            float2 sb = *(const float2*)(g_srel1 + ca.w*2);
            sr0a = sa.x + sb.x; sr1a = sa.y + sb.y;
        }
        float ee0 = __expf(-lrelu(ssn.x + sda.x + sr0a));
        float ee1 = __expf(-lrelu(ssn.y + sda.y + sr1a));
        rs0 += ee0; rs1 += ee1;
        fma4(wx0, ee0, xva); fma4(wx1, ee1, xva);
        fma4(we0, ee0, eva); fma4(we1, ee1, eva);
    }

    float i0 = (end > beg) ? (1.f / rs0) : 0.f;
    float i1 = (end > beg) ? (1.f / rs1) : 0.f;
    float4* c4 = (float4*)g_cat1;
    size_t b = (size_t)w*128;
    __stcs(&c4[b +  0 + l], make_float4(wx0.x*i0, wx0.y*i0, wx0.z*i0, wx0.w*i0));
    __stcs(&c4[b + 32 + l], make_float4(we0.x*i0, we0.y*i0, we0.z*i0, we0.w*i0));
    __stcs(&c4[b + 64 + l], make_float4(wx1.x*i1, wx1.y*i1, wx1.z*i1, wx1.w*i1));
    __stcs(&c4[b + 96 + l], make_float4(we1.x*i1, we1.y*i1, we1.z*i1, we1.w*i1));
}

// ---------------- layer 2 edge pass (x2 unroll) ----------------
__global__ void k_edge2(){
    int w = (blockIdx.x*blockDim.x + threadIdx.x) >> 5;
    int l = threadIdx.x & 31;
    if (w >= NN) return;
    int beg = g_rp[w], end = g_rp[w+1];

    const float4* x4 = (const float4*)g_x2;
    const float4* o4 = (const float4*)g_outrel;
    float ssn = g_s2s[w];

    float4 wx = {0,0,0,0}, wo = {0,0,0,0}, sx = {0,0,0,0}, so = {0,0,0,0};
    float rs = 0.f;

    int p = beg;
    for (; p + 1 < end; p += 2){
        int4 ca = __ldcs(&g_meta[p]);
        int4 cb = __ldcs(&g_meta[p+1]);
        float4 xva = x4[(size_t)ca.x*32 + l];
        float4 xvb = x4[(size_t)cb.x*32 + l];
        float sda = g_s2d[ca.x];
        float sdb = g_s2d[cb.x];
        float4 ova, ovb;
        float sra, srb;
        if (ca.w < 0){ ova = o4[ca.z*32 + l]; sra = g_s2rel[ca.z]; }
        else {
            float4 ra = o4[ca.z*32 + l], rb = o4[ca.w*32 + l];
            ova = make_float4(ra.x+rb.x, ra.y+rb.y, ra.z+rb.z, ra.w+rb.w);
            sra = g_s2rel[ca.z] + g_s2rel[ca.w];
        }
        if (cb.w < 0){ ovb = o4[cb.z*32 + l]; srb = g_s2rel[cb.z]; }
        else {
            float4 ra = o4[cb.z*32 + l], rb = o4[cb.w*32 + l];
            ovb = make_float4(ra.x+rb.x, ra.y+rb.y, ra.z+rb.z, ra.w+rb.w);
            srb = g_s2rel[cb.z] + g_s2rel[cb.w];
        }
        float eea = __expf(-lrelu(ssn + sda + sra));
        float eeb = __expf(-lrelu(ssn + sdb + srb));
        rs += eea + eeb;
        fma4(wx, eea, xva); fma4(wx, eeb, xvb);
        fma4(wo, eea, ova); fma4(wo, eeb, ovb);
        sx.x += xva.x + xvb.x; sx.y += xva.y + xvb.y;
        sx.z += xva.z + xvb.z; sx.w += xva.w + xvb.w;
        so.x += ova.x + ovb.x; so.y += ova.y + ovb.y;
        so.z += ova.z + ovb.z; so.w += ova.w + ovb.w;
    }
    if (p < end){
        int4 ca = __ldcs(&g_meta[p]);
        float4 xva = x4[(size_t)ca.x*32 + l];
        float sda = g_s2d[ca.x];
        float4 ova; float sra;
        if (ca.w < 0){ ova = o4[ca.z*32 + l]; sra = g_s2rel[ca.z]; }
        else {
            float4 ra = o4[ca.z*32 + l], rb = o4[ca.w*32 + l];
            ova = make_float4(ra.x+rb.x, ra.y+rb.y, ra.z+rb.z, ra.w+rb.w);
            sra = g_s2rel[ca.z] + g_s2rel[ca.w];
        }
        float eea = __expf(-lrelu(ssn + sda + sra));
        rs += eea;
        fma4(wx, eea, xva); fma4(wo, eea, ova);
        sx.x += xva.x; sx.y += xva.y; sx.z += xva.z; sx.w += xva.w;
        so.x += ova.x; so.y += ova.y; so.z += ova.z; so.w += ova.w;
    }

    int cnt = end - beg;
    float ic = cnt ? (1.f / (float)cnt) : 0.f;
    float4* a4 = (float4*)g_acc2;
    size_t b = (size_t)w*128;
    __stcs(&a4[b +  0 + l], wx);
    __stcs(&a4[b + 32 + l], wo);
    __stcs(&a4[b + 64 + l], make_float4(sx.x*ic, sx.y*ic, sx.z*ic, sx.w*ic));
    __stcs(&a4[b + 96 + l], make_float4(so.x*ic, so.y*ic, so.z*ic, so.w*ic));
    if (l == 0) g_rs2[w] = rs;
}

// ---------------- layer-1 GEMM: x2 = elu([x | cat1_h] @ a_heads_h^T), BN=64 ----------------
__global__ __launch_bounds__(256) void k_tgemm1(const float* __restrict__ Aext){
    const int h = blockIdx.y;
    const float* A1 = Aext;                    // x, lda 128
    const float* A2 = g_cat1 + h*256;          // lda 512
    const __nv_bfloat16* Bh = g_Bh1 + h*24576;
    const __nv_bfloat16* Bl = g_Bl1 + h*24576;
    const int K1 = 128, K = 384, M = NN;
    constexpr int BN = 64, NF = BN/16;

    __shared__ __align__(16) __nv_bfloat16 Ah[128][40];
    __shared__ __align__(16) __nv_bfloat16 Al[128][40];
    __shared__ __align__(16) __nv_bfloat16 Bhs[BN][40];
    __shared__ __align__(16) __nv_bfloat16 Bls[BN][40];

    int tid = threadIdx.x, lane = tid & 31, warp = tid >> 5;
    int wm = (warp & 3) * 32;
    int wn = (warp >> 2) * (BN/2);
    int bm0 = blockIdx.x * 128;

    float d[2][NF][4];
    #pragma unroll
    for (int f = 0; f < 2; f++)
        #pragma unroll
        for (int j = 0; j < NF; j++)
            #pragma unroll
            for (int q = 0; q < 4; q++) d[f][j][q] = 0.f;

    int ar = tid >> 1, akq = (tid & 1) * 16;
    int bn = tid / 4, bkq = (tid % 4) * 8;
    int m = bm0 + ar;
    bool mv = m < M;

    for (int k0 = 0; k0 < K; k0 += 32){
        const float* asrc;
        bool strm;
        if (k0 < K1){ asrc = A1 + (size_t)m*128 + k0 + akq; strm = false; }
        else        { asrc = A2 + (size_t)m*512 + (k0-K1) + akq; strm = true; }
        #pragma unroll
        for (int j = 0; j < 16; j += 4){
            float4 v = make_float4(0,0,0,0);
            if (mv) v = strm ? __ldcs((const float4*)(asrc + j))
                             : *(const float4*)(asrc + j);
            __nv_bfloat162 h0 = __floats2bfloat162_rn(v.x, v.y);
            __nv_bfloat162 h1 = __floats2bfloat162_rn(v.z, v.w);
            __nv_bfloat162 l0 = __floats2bfloat162_rn(v.x - __low2float(h0),
                                                      v.y - __high2float(h0));
            __nv_bfloat162 l1 = __floats2bfloat162_rn(v.z - __low2float(h1),
                                                      v.w - __high2float(h1));
            *(__nv_bfloat162*)&Ah[ar][akq+j]   = h0;
            *(__nv_bfloat162*)&Ah[ar][akq+j+2] = h1;
            *(__nv_bfloat162*)&Al[ar][akq+j]   = l0;
            *(__nv_bfloat162*)&Al[ar][akq+j+2] = l1;
        }
        *(uint4*)&Bhs[bn][bkq] = *(const uint4*)(Bh + (size_t)bn*384 + k0 + bkq);
        *(uint4*)&Bls[bn][bkq] = *(const uint4*)(Bl + (size_t)bn*384 + k0 + bkq);
        __syncthreads();

        #pragma unroll
        for (int kk = 0; kk < 32; kk += 16){
            unsigned ah_[2][4], al_[2][4], bh_[NF][2], bl_[NF][2];
            #pragma unroll
            for (int f = 0; f < 2; f++){
                int rrow = wm + f*16 + (lane & 15);
                int rcol = kk + (lane >> 4) * 8;
                ldsm4(ah_[f][0], ah_[f][1], ah_[f][2], ah_[f][3], smem_u32(&Ah[rrow][rcol]));
                ldsm4(al_[f][0], al_[f][1], al_[f][2], al_[f][3], smem_u32(&Al[rrow][rcol]));
            }
            #pragma unroll
            for (int g = 0; g < NF/2; g++){
                int nb = wn + g*16 + ((lane >> 4) << 3) + (lane & 7);
                int kc = kk + ((lane >> 3) & 1) * 8;
                ldsm4(bh_[2*g][0], bh_[2*g][1], bh_[2*g+1][0], bh_[2*g+1][1], smem_u32(&Bhs[nb][kc]));
                ldsm4(bl_[2*g][0], bl_[2*g][1], bl_[2*g+1][0], bl_[2*g+1][1], smem_u32(&Bls[nb][kc]));
            }
            #pragma unroll
            for (int f = 0; f < 2; f++)
                #pragma unroll
                for (int j = 0; j < NF; j++){
                    mmabf(d[f][j], ah_[f], bh_[j]);
                    mmabf(d[f][j], ah_[f], bl_[j]);
                    mmabf(d[f][j], al_[f], bh_[j]);
                }
        }
        __syncthreads();
    }

    int gid = lane >> 2, tig = lane & 3;
    #pragma unroll
    for (int f = 0; f < 2; f++){
        #pragma unroll
        for (int j = 0; j < NF; j++){
            int col = h*64 + wn + j*8 + tig*2;
            int m0r = bm0 + wm + f*16 + gid;
            #pragma unroll
            for (int half = 0; half < 2; half++){
                int mm = m0r + half*8;
                if (mm >= M) continue;
                bool live = (g_rp[mm+1] - g_rp[mm]) > 0;
                float v0 = live ? eluf(d[f][j][half*2+0]) : 0.f;
                float v1 = live ? eluf(d[f][j][half*2+1]) : 0.f;
                *(float2*)&g_x2[(size_t)mm*128 + col] = make_float2(v0, v1);
            }
        }
    }
}

// ---------------- layer-2 fused GEMM: hn/un with direct output epilogue ----------------
__global__ __launch_bounds__(256) void k_tgemm2(float* __restrict__ out){
    const int which = blockIdx.y;
    const float* A2 = g_acc2 + (which ? 256 : 0);
    const int K1 = 128, K = 384, M = NN;
    constexpr int BN = 128, NF = BN/16;

    __shared__ __align__(16) __nv_bfloat16 Ah[128][40];
    __shared__ __align__(16) __nv_bfloat16 Al[128][40];
    __shared__ __align__(16) __nv_bfloat16 Bhs[BN][40];
    __shared__ __align__(16) __nv_bfloat16 Bls[BN][40];

    int tid = threadIdx.x, lane = tid & 31, warp = tid >> 5;
    int wm = (warp & 3) * 32;
    int wn = (warp >> 2) * 64;
    int bm0 = blockIdx.x * 128;

    float d[2][NF][4];
    #pragma unroll
    for (int f = 0; f < 2; f++)
        #pragma unroll
        for (int j = 0; j < NF; j++)
            #pragma unroll
            for (int q = 0; q < 4; q++) d[f][j][q] = 0.f;

    int ar = tid >> 1, akq = (tid & 1) * 16;
    int bn = tid / 2, bkq = (tid & 1) * 16;
    int m = bm0 + ar;
    bool mv = m < M;
    float scl = 1.f;
    if (which == 0 && mv) scl = g_rs2[m];   // hn: rs-scaled x2 rows

    for (int k0 = 0; k0 < K; k0 += 32){
        const float* asrc;
        bool strm; float s;
        if (k0 < K1){ asrc = g_x2 + (size_t)m*128 + k0 + akq; strm = false; s = scl; }
        else        { asrc = A2 + (size_t)m*512 + (k0-K1) + akq; strm = true; s = 1.f; }
        #pragma unroll
        for (int j = 0; j < 16; j += 4){
            float4 v = make_float4(0,0,0,0);
            if (mv) v = strm ? __ldcs((const float4*)(asrc + j))
                             : *(const float4*)(asrc + j);
            v.x *= s; v.y *= s; v.z *= s; v.w *= s;
            __nv_bfloat162 h0 = __floats2bfloat162_rn(v.x, v.y);
            __nv_bfloat162 h1 = __floats2bfloat162_rn(v.z, v.w);
            __nv_bfloat162 l0 = __floats2bfloat162_rn(v.x - __low2float(h0),
                                                      v.y - __high2float(h0));
            __nv_bfloat162 l1 = __floats2bfloat162_rn(v.z - __low2float(h1),
                                                      v.w - __high2float(h1));
            *(__nv_bfloat162*)&Ah[ar][akq+j]   = h0;
            *(__nv_bfloat162*)&Ah[ar][akq+j+2] = h1;
            *(__nv_bfloat162*)&Al[ar][akq+j]   = l0;
            *(__nv_bfloat162*)&Al[ar][akq+j+2] = l1;
        }
        #pragma unroll
        for (int j = 0; j < 16; j += 8){
            *(uint4*)&Bhs[bn][bkq+j] = *(const uint4*)(g_Bh2 + (size_t)bn*384 + k0 + bkq + j);
            *(uint4*)&Bls[bn][bkq+j] = *(const uint4*)(g_Bl2 + (size_t)bn*384 + k0 + bkq + j);
        }
        __syncthreads();

        #pragma unroll
        for (int kk = 0; kk < 32; kk += 16){
            unsigned ah_[2][4], al_[2][4], bh_[NF][2], bl_[NF][2];
            #pragma unroll
            for (int f = 0; f < 2; f++){
                int rrow = wm + f*16 + (lane & 15);
                int rcol = kk + (lane >> 4) * 8;
                ldsm4(ah_[f][0], ah_[f][1], ah_[f][2], ah_[f][3], smem_u32(&Ah[rrow][rcol]));
                ldsm4(al_[f][0], al_[f][1], al_[f][2], al_[f][3], smem_u32(&Al[rrow][rcol]));
            }
            #pragma unroll
            for (int g = 0; g < NF/2; g++){
                int nb = wn + g*16 + ((lane >> 4) << 3) + (lane & 7);
                int kc = kk + ((lane >> 3) & 1) * 8;
                ldsm4(bh_[2*g][0], bh_[2*g][1], bh_[2*g+1][0], bh_[2*g+1][1], smem_u32(&Bhs[nb][kc]));
                ldsm4(bl_[2*g][0], bl_[2*g][1], bl_[2*g+1][0], bl_[2*g+1][1], smem_u32(&Bls[nb][kc]));
            }
            #pragma unroll
            for (int f = 0; f < 2; f++)
                #pragma unroll
                for (int j = 0; j < NF; j++){
                    mmabf(d[f][j], ah_[f], bh_[j]);
                    mmabf(d[f][j], ah_[f], bl_[j]);
                    mmabf(d[f][j], al_[f], bh_[j]);
                }
        }
        __syncthreads();
    }

    // fused epilogue -> d_out
    int gid = lane >> 2, tig = lane & 3;
    #pragma unroll
    for (int f = 0; f < 2; f++){
        #pragma unroll
        for (int half = 0; half < 2; half++){
            int mm = bm0 + wm + f*16 + gid + half*8;
            if (mm >= M) continue;
            float inv = 0.f;
            if (which == 0){
                float rs = g_rs2[mm];
                inv = (rs > 0.f) ? (1.f / rs) : 0.f;
            }
            #pragma unroll
            for (int j = 0; j < NF; j++){
                int col = wn + j*8 + tig*2;
                float v0 = d[f][j][half*2+0];
                float v1 = d[f][j][half*2+1];
                size_t o = (size_t)mm*128 + col;
                if (which == 0){
                    __stcs((float2*)&out[o],        make_float2(eluf(v0*inv), eluf(v1*inv)));
                    __stcs((float2*)&out[OFF2 + o], make_float2(eluf(v0),     eluf(v1)));
                } else {
                    __stcs((float2*)&out[OFF3 + o], make_float2(eluf(v0), eluf(v1)));
                }
            }
        }
    }
}

// ---------------- launcher ----------------
extern "C" void kernel_launch(void* const* d_in, const int* in_sizes, int n_in,
                              void* d_out, int out_size){
    const float* x    = (const float*)d_in[0];
    const float* rel  = (const float*)d_in[1];
    const float* eemb = (const float*)d_in[2];
    const float* ah   = (const float*)d_in[3];
    const float* a2h  = (const float*)d_in[4];
    const float* W    = (const float*)d_in[5];
    const float* ao   = (const float*)d_in[6];
    const float* a2o  = (const float*)d_in[7];
    const int* el  = (const int*)d_in[8];
    const int* et  = (const int*)d_in[9];
    const int* eln = (const int*)d_in[10];
    const int* etn = (const int*)d_in[11];
    float* out = (float*)d_out;

    const int GB = (NN + 127) / 128;   // 391

    // CSR build (g_cnt arrives zeroed: zero-init + self-clean in k_scan)
    k_hist<<<(NET + 255)/256, 256>>>(el, eln);
    k_scan<<<1, 1024>>>();
    k_scatter<<<(NET + 255)/256, 256>>>(el, et, eln, etn);

    // small precompute
    k_prep<<<(99456 + 255)/256, 256>>>(ah, a2h, ao, a2o);
    k_outrel<<<(NREL*128 + 255)/256, 256>>>(rel, W, out);
    k_srel<<<(1500 + 255)/256, 256>>>(rel);

    // layer 1
    k_sdots1<<<6250, 256>>>(x);
    k_edge1<<<6250, 256>>>(x, eemb, rel);
    k_tgemm1<<<dim3(GB, 2), 256>>>(x);

    // layer 2
    k_sdots2<<<6250, 256>>>();
    k_edge2<<<6250, 256>>>();
    k_tgemm2<<<dim3(GB, 2), 256>>>(out);
}